// round 4
// baseline (speedup 1.0000x reference)
#include <cuda_runtime.h>

// ---------------- problem constants (pinned by the dataset) ----------------
#define B_    32768
#define H_    512
#define MD_   8
#define CD_   1024
#define KIN   532          // H + 20
#define KP    544          // KIN padded to multiple of 8 (and 16B)
#define NCAT_ 262144
#define EPS_  1e-6f

// ---------------- scratch (static device allocations only) -----------------
__device__ float g_sums[B_ * MD_];          // segment sums        [B,8]
__device__ float g_counts[B_];              // segment counts      [B]
__device__ float g_meta[B_ * 20];           // meta features       [B,20]
__device__ float g_bias[B_ * 6];            // normalized credit   [B,6]
__device__ float g_xn[(size_t)B_ * KP];     // LN1(mlp_input), K-padded [B,544]
__device__ float g_w1p[KP * CD_];           // mlp1_w transposed+padded [544,1024]
__device__ float g_feat[(size_t)B_ * CD_];  // relu(GEMM1) [B,1024]

// ---------------- kernel 0: zero segment scratch ----------------
__global__ void zero_kernel() {
    int i = blockIdx.x * blockDim.x + threadIdx.x;
    int n = B_ * MD_ + B_;
    for (; i < n; i += gridDim.x * blockDim.x) {
        if (i < B_ * MD_) g_sums[i] = 0.f;
        else              g_counts[i - B_ * MD_] = 0.f;
    }
}

// ---------------- kernel 1: ragged segment sums (sorted segs, atomics) -----
__global__ void seg_kernel(const float* __restrict__ table,
                           const int* __restrict__ cat_ids,
                           const int* __restrict__ cat_seg) {
    int i = blockIdx.x * blockDim.x + threadIdx.x;
    if (i >= NCAT_) return;
    int cid = cat_ids[i];
    int seg = cat_seg[i];
    const float4* t4 = (const float4*)(table + (size_t)cid * MD_);
    float4 a = t4[0], b = t4[1];
    float* dst = g_sums + (size_t)seg * MD_;
    atomicAdd(dst + 0, a.x); atomicAdd(dst + 1, a.y);
    atomicAdd(dst + 2, a.z); atomicAdd(dst + 3, a.w);
    atomicAdd(dst + 4, b.x); atomicAdd(dst + 5, b.y);
    atomicAdd(dst + 6, b.z); atomicAdd(dst + 7, b.w);
    atomicAdd(&g_counts[seg], 1.0f);
}

// ---------------- kernel 2: meta conv/pool features + credit biases --------
__global__ void meta_kernel(const float* __restrict__ table,
                            const float* __restrict__ credit,
                            const float* __restrict__ conv_w,
                            const float* __restrict__ conv_b,
                            const int* __restrict__ meta_ids) {
    int b = blockIdx.x * blockDim.x + threadIdx.x;
    if (b >= B_) return;

    float mat[6][MD_];
    float cnt = fmaxf(g_counts[b], 1.0f);
    float inv = 1.0f / cnt;
    #pragma unroll
    for (int d = 0; d < MD_; d++) mat[0][d] = g_sums[(size_t)b * MD_ + d] * inv;
    #pragma unroll
    for (int j = 0; j < 5; j++) {
        int id = meta_ids[b * 5 + j];
        const float* row = table + (size_t)id * MD_;
        #pragma unroll
        for (int d = 0; d < MD_; d++) mat[j + 1][d] = row[d];
    }

    // Conv1d(6->5, k=3, VALID) + ReLU + MaxPool1d(3,1)
    #pragma unroll
    for (int c = 0; c < 5; c++) {
        float conv[6];
        #pragma unroll
        for (int t = 0; t < 6; t++) {
            float s = conv_b[c];
            #pragma unroll
            for (int i = 0; i < 6; i++) {
                #pragma unroll
                for (int k = 0; k < 3; k++)
                    s += conv_w[c * 18 + i * 3 + k] * mat[i][t + k];
            }
            conv[t] = fmaxf(s, 0.f);
        }
        #pragma unroll
        for (int t = 0; t < 4; t++)
            g_meta[(size_t)b * 20 + c * 4 + t] =
                fmaxf(fmaxf(conv[t], conv[t + 1]), conv[t + 2]);
    }

    float cv[6], s = 0.f;
    #pragma unroll
    for (int c = 0; c < 6; c++) { cv[c] = credit[b * 6 + c]; s += cv[c]; }
    float invs = (s > 0.f) ? (1.0f / s) : 0.f;
    #pragma unroll
    for (int c = 0; c < 6; c++)
        g_bias[(size_t)b * 6 + c] = (s > 0.f) ? cv[c] * invs : (1.0f / 6.0f);
}

// ---------------- kernel 3: LN1 over concat(encode, meta_feat) -------------
// one block (128 threads) per row; writes K-padded normalized input
__global__ void ln1_kernel(const float* __restrict__ encode,
                           const float* __restrict__ g1,
                           const float* __restrict__ b1) {
    int row = blockIdx.x;
    int tid = threadIdx.x;              // 0..127
    int lane = tid & 31, wid = tid >> 5;

    float4 x = ((const float4*)(encode + (size_t)row * H_))[tid];
    float mv = (tid < 20) ? g_meta[(size_t)row * 20 + tid] : 0.f;
    float s  = x.x + x.y + x.z + x.w + mv;
    float sq = x.x * x.x + x.y * x.y + x.z * x.z + x.w * x.w + mv * mv;

    #pragma unroll
    for (int o = 16; o > 0; o >>= 1) {
        s  += __shfl_down_sync(0xffffffffu, s, o);
        sq += __shfl_down_sync(0xffffffffu, sq, o);
    }
    __shared__ float rs[4], rq[4], st[2];
    if (lane == 0) { rs[wid] = s; rq[wid] = sq; }
    __syncthreads();
    if (tid == 0) {
        float S = rs[0] + rs[1] + rs[2] + rs[3];
        float Q = rq[0] + rq[1] + rq[2] + rq[3];
        float mean = S / (float)KIN;
        float var  = Q / (float)KIN - mean * mean;
        st[0] = mean;
        st[1] = rsqrtf(var + EPS_);
    }
    __syncthreads();
    float mean = st[0], rstd = st[1];

    float* xo = g_xn + (size_t)row * KP;
    float4 gg = ((const float4*)g1)[tid];
    float4 bb = ((const float4*)b1)[tid];
    float4 o;
    o.x = (x.x - mean) * rstd * gg.x + bb.x;
    o.y = (x.y - mean) * rstd * gg.y + bb.y;
    o.z = (x.z - mean) * rstd * gg.z + bb.z;
    o.w = (x.w - mean) * rstd * gg.w + bb.w;
    ((float4*)xo)[tid] = o;
    if (tid < 20) {
        int k = H_ + tid;
        xo[k] = (mv - mean) * rstd * g1[k] + b1[k];
    }
    if (tid < KP - KIN) xo[KIN + tid] = 0.f;   // zero pad
}

// ---------------- kernel 4: transpose + pad mlp1_w -> [KP,1024] ------------
__global__ void w1t_kernel(const float* __restrict__ w1) {
    int idx = blockIdx.x * blockDim.x + threadIdx.x;
    if (idx >= KP * CD_) return;
    int n = idx % CD_;
    int k = idx / CD_;
    g_w1p[idx] = (k < KIN) ? w1[(size_t)n * KIN + k] : 0.f;
}

// ---------------- kernel 5: SGEMM1 + bias + ReLU ---------------------------
// C[B,1024] = relu(Xn[B,544] @ W1p[544,1024] + b1)
#define BM 128
#define BN 128
#define BKK 8
__global__ __launch_bounds__(256) void gemm1_kernel(const float* __restrict__ b1) {
    __shared__ float As[BKK][BM];
    __shared__ float Bs[BKK][BN];
    const int tid = threadIdx.x;
    const int tx = tid & 15;        // n-dim
    const int ty = tid >> 4;        // m-dim
    const int m0 = blockIdx.y * BM;
    const int n0 = blockIdx.x * BN;

    const int ar = tid >> 1;                 // 0..127
    const int ak = (tid & 1) * 4;            // 0 or 4
    const int bk = tid >> 5;                 // 0..7
    const int bn = (tid & 31) * 4;           // 0..124

    const float* Aptr = g_xn  + (size_t)(m0 + ar) * KP + ak;
    const float* Bptr = g_w1p + (size_t)bk * CD_ + n0 + bn;

    float acc[8][8];
    #pragma unroll
    for (int i = 0; i < 8; i++)
        #pragma unroll
        for (int j = 0; j < 8; j++) acc[i][j] = 0.f;

    for (int k0 = 0; k0 < KP; k0 += BKK) {
        float4 av = *(const float4*)(Aptr + k0);
        float4 bv = *(const float4*)(Bptr + (size_t)k0 * CD_);
        __syncthreads();
        As[ak + 0][ar] = av.x;
        As[ak + 1][ar] = av.y;
        As[ak + 2][ar] = av.z;
        As[ak + 3][ar] = av.w;
        *(float4*)&Bs[bk][bn] = bv;
        __syncthreads();
        #pragma unroll
        for (int kk = 0; kk < BKK; kk++) {
            float4 a0 = *(const float4*)&As[kk][ty * 8];
            float4 a1 = *(const float4*)&As[kk][ty * 8 + 4];
            float4 c0 = *(const float4*)&Bs[kk][tx * 8];
            float4 c1 = *(const float4*)&Bs[kk][tx * 8 + 4];
            float ra[8] = {a0.x, a0.y, a0.z, a0.w, a1.x, a1.y, a1.z, a1.w};
            float rb[8] = {c0.x, c0.y, c0.z, c0.w, c1.x, c1.y, c1.z, c1.w};
            #pragma unroll
            for (int i = 0; i < 8; i++)
                #pragma unroll
                for (int j = 0; j < 8; j++)
                    acc[i][j] += ra[i] * rb[j];
        }
    }

    float bl[8];
    #pragma unroll
    for (int j = 0; j < 8; j++) bl[j] = b1[n0 + tx * 8 + j];

    #pragma unroll
    for (int i = 0; i < 8; i++) {
        size_t row = (size_t)(m0 + ty * 8 + i);
        float* dst = g_feat + row * CD_ + n0 + tx * 8;
        float4 v0, v1;
        v0.x = fmaxf(acc[i][0] + bl[0], 0.f);
        v0.y = fmaxf(acc[i][1] + bl[1], 0.f);
        v0.z = fmaxf(acc[i][2] + bl[2], 0.f);
        v0.w = fmaxf(acc[i][3] + bl[3], 0.f);
        v1.x = fmaxf(acc[i][4] + bl[4], 0.f);
        v1.y = fmaxf(acc[i][5] + bl[5], 0.f);
        v1.z = fmaxf(acc[i][6] + bl[6], 0.f);
        v1.w = fmaxf(acc[i][7] + bl[7], 0.f);
        *(float4*)(dst + 0) = v0;
        *(float4*)(dst + 4) = v1;
    }
}

// ---------------- kernel 6: LN2 + out GEMM + out_b + biases ----------------
// one block (256 thr) handles 8 rows
#define FROWS 8
__global__ __launch_bounds__(256) void final_kernel(const float* __restrict__ ln2g,
                                                    const float* __restrict__ ln2b,
                                                    const float* __restrict__ out_w,
                                                    const float* __restrict__ out_b,
                                                    float* __restrict__ out) {
    const int tid = threadIdx.x;    // 0..255
    const int lane = tid & 31, wid = tid >> 5;
    const int k0 = tid * 4;

    // hoist per-thread constants: ln2 params and out_w columns
    float4 gg = ((const float4*)ln2g)[tid];
    float4 bb = ((const float4*)ln2b)[tid];
    float wreg[6][4];
    #pragma unroll
    for (int c = 0; c < 6; c++) {
        float4 w = *(const float4*)(out_w + (size_t)c * CD_ + k0);
        wreg[c][0] = w.x; wreg[c][1] = w.y; wreg[c][2] = w.z; wreg[c][3] = w.w;
    }

    __shared__ float rs[8], rq[8], st[2], accs[8][6];

    int row0 = blockIdx.x * FROWS;
    for (int r = 0; r < FROWS; r++) {
        int row = row0 + r;
        float4 xv = ((const float4*)(g_feat + (size_t)row * CD_))[tid];
        float s  = xv.x + xv.y + xv.z + xv.w;
        float sq = xv.x * xv.x + xv.y * xv.y + xv.z * xv.z + xv.w * xv.w;
        #pragma unroll
        for (int o = 16; o > 0; o >>= 1) {
            s  += __shfl_down_sync(0xffffffffu, s, o);
            sq += __shfl_down_sync(0xffffffffu, sq, o);
        }
        if (lane == 0) { rs[wid] = s; rq[wid] = sq; }
        __syncthreads();
        if (tid == 0) {
            float S = 0.f, Q = 0.f;
            #pragma unroll
            for (int w = 0; w < 8; w++) { S += rs[w]; Q += rq[w]; }
            float mean = S / (float)CD_;
            float var  = Q / (float)CD_ - mean * mean;
            st[0] = mean;
            st[1] = rsqrtf(var + EPS_);
        }
        __syncthreads();
        float mean = st[0], rstd = st[1];

        float xn[4];
        xn[0] = (xv.x - mean) * rstd * gg.x + bb.x;
        xn[1] = (xv.y - mean) * rstd * gg.y + bb.y;
        xn[2] = (xv.z - mean) * rstd * gg.z + bb.z;
        xn[3] = (xv.w - mean) * rstd * gg.w + bb.w;

        float a[6] = {0.f, 0.f, 0.f, 0.f, 0.f, 0.f};
        #pragma unroll
        for (int j = 0; j < 4; j++)
            #pragma unroll
            for (int c = 0; c < 6; c++)
                a[c] += xn[j] * wreg[c][j];

        #pragma unroll
        for (int o = 16; o > 0; o >>= 1)
            #pragma unroll
            for (int c = 0; c < 6; c++)
                a[c] += __shfl_down_sync(0xffffffffu, a[c], o);
        if (lane == 0) {
            #pragma unroll
            for (int c = 0; c < 6; c++) accs[wid][c] = a[c];
        }
        __syncthreads();
        if (tid < 6) {
            float t = 0.f;
            #pragma unroll
            for (int w = 0; w < 8; w++) t += accs[w][tid];
            out[(size_t)row * 6 + tid] = t + out_b[tid] + g_bias[(size_t)row * 6 + tid];
        }
        __syncthreads();
    }
}

// ---------------- launch ---------------------------------------------------
extern "C" void kernel_launch(void* const* d_in, const int* in_sizes, int n_in,
                              void* d_out, int out_size) {
    const float* encode     = (const float*)d_in[0];
    const float* credit_vec = (const float*)d_in[1];
    const float* meta_table = (const float*)d_in[2];
    const float* conv_w     = (const float*)d_in[3];
    const float* conv_b     = (const float*)d_in[4];
    const float* ln1_g      = (const float*)d_in[5];
    const float* ln1_b      = (const float*)d_in[6];
    const float* mlp1_w     = (const float*)d_in[7];
    const float* mlp1_b     = (const float*)d_in[8];
    const float* ln2_g      = (const float*)d_in[9];
    const float* ln2_b      = (const float*)d_in[10];
    const float* out_w      = (const float*)d_in[11];
    const float* out_b      = (const float*)d_in[12];
    const int*   meta_ids   = (const int*)d_in[13];
    const int*   cat_ids    = (const int*)d_in[14];
    const int*   cat_seg    = (const int*)d_in[15];
    float*       out        = (float*)d_out;

    zero_kernel<<<512, 256>>>();
    seg_kernel<<<NCAT_ / 256, 256>>>(meta_table, cat_ids, cat_seg);
    meta_kernel<<<B_ / 256, 256>>>(meta_table, credit_vec, conv_w, conv_b, meta_ids);
    ln1_kernel<<<B_, 128>>>(encode, ln1_g, ln1_b);
    w1t_kernel<<<(KP * CD_ + 255) / 256, 256>>>(mlp1_w);
    {
        dim3 grid(CD_ / BN, B_ / BM);
        gemm1_kernel<<<grid, 256>>>(mlp1_b);
    }
    final_kernel<<<B_ / FROWS, 256>>>(ln2_g, ln2_b, out_w, out_b, out);
}

// round 8
// speedup vs baseline: 3.5514x; 3.5514x over previous
#include <cuda_runtime.h>
#include <cstdint>

// ---------------- problem constants (pinned by the dataset) ----------------
#define B_    32768
#define H_    512
#define MD_   8
#define CD_   1024
#define KIN   532          // H + 20
#define KP    544          // KIN padded to 17 * 32
#define NCAT_ 262144
#define EPS_  1e-6f

// ---------------- scratch (static device allocations only) -----------------
__device__ __align__(128) float g_sums[B_ * MD_];
__device__ float g_counts[B_];
__device__ float g_meta[B_ * 20];
__device__ float g_bias[B_ * 6];
__device__ __align__(128) float g_xn[(size_t)B_ * KP];    // LN1 output, tf32-rounded, padded
__device__ __align__(128) float g_w1p[CD_ * KP];          // mlp1_w [1024][544] tf32-rounded, padded
__device__ __align__(128) float g_feat[(size_t)B_ * CD_]; // relu(GEMM1)

// ---------------- PTX helpers (baseline ISA only, no 'a' features) ---------
__device__ __forceinline__ uint32_t smem_u32(const void* p) {
    uint32_t a;
    asm("{ .reg .u64 t; cvta.to.shared.u64 t, %1; cvt.u32.u64 %0, t; }" : "=r"(a) : "l"(p));
    return a;
}
__device__ __forceinline__ float rnd_tf32(float x) {
    float o;
    asm("cvt.rna.tf32.f32 %0, %1;" : "=f"(o) : "f"(x));
    return o;
}
__device__ __forceinline__ void cp_async16(uint32_t saddr, const void* gaddr) {
    asm volatile("cp.async.cg.shared.global [%0], [%1], 16;" :: "r"(saddr), "l"(gaddr));
}
__device__ __forceinline__ void cp_commit() {
    asm volatile("cp.async.commit_group;");
}
template <int N>
__device__ __forceinline__ void cp_wait() {
    asm volatile("cp.async.wait_group %0;" :: "n"(N) : "memory");
}
__device__ __forceinline__ void mma_tf32(float* c, const uint32_t* a, const uint32_t* b) {
    asm volatile(
        "mma.sync.aligned.m16n8k8.row.col.f32.tf32.tf32.f32 "
        "{%0,%1,%2,%3}, {%4,%5,%6,%7}, {%8,%9}, {%0,%1,%2,%3};"
        : "+f"(c[0]), "+f"(c[1]), "+f"(c[2]), "+f"(c[3])
        : "r"(a[0]), "r"(a[1]), "r"(a[2]), "r"(a[3]), "r"(b[0]), "r"(b[1]));
}

// ---------------- kernel 0: zero segment scratch ----------------
__global__ void zero_kernel() {
    int i = blockIdx.x * blockDim.x + threadIdx.x;
    int n = B_ * MD_ + B_;
    for (; i < n; i += gridDim.x * blockDim.x) {
        if (i < B_ * MD_) g_sums[i] = 0.f;
        else              g_counts[i - B_ * MD_] = 0.f;
    }
}

// ---------------- kernel 1: ragged segment sums ----------------
__global__ void seg_kernel(const float* __restrict__ table,
                           const int* __restrict__ cat_ids,
                           const int* __restrict__ cat_seg) {
    int i = blockIdx.x * blockDim.x + threadIdx.x;
    if (i >= NCAT_) return;
    int cid = cat_ids[i];
    int seg = cat_seg[i];
    const float4* t4 = (const float4*)(table + (size_t)cid * MD_);
    float4 a = t4[0], b = t4[1];
    float* dst = g_sums + (size_t)seg * MD_;
    atomicAdd(dst + 0, a.x); atomicAdd(dst + 1, a.y);
    atomicAdd(dst + 2, a.z); atomicAdd(dst + 3, a.w);
    atomicAdd(dst + 4, b.x); atomicAdd(dst + 5, b.y);
    atomicAdd(dst + 6, b.z); atomicAdd(dst + 7, b.w);
    atomicAdd(&g_counts[seg], 1.0f);
}

// ---------------- kernel 2: meta conv/pool features + credit biases --------
__global__ void meta_kernel(const float* __restrict__ table,
                            const float* __restrict__ credit,
                            const float* __restrict__ conv_w,
                            const float* __restrict__ conv_b,
                            const int* __restrict__ meta_ids) {
    int b = blockIdx.x * blockDim.x + threadIdx.x;
    if (b >= B_) return;

    float mat[6][MD_];
    float cnt = fmaxf(g_counts[b], 1.0f);
    float inv = 1.0f / cnt;
    #pragma unroll
    for (int d = 0; d < MD_; d++) mat[0][d] = g_sums[(size_t)b * MD_ + d] * inv;
    #pragma unroll
    for (int j = 0; j < 5; j++) {
        int id = meta_ids[b * 5 + j];
        const float* row = table + (size_t)id * MD_;
        #pragma unroll
        for (int d = 0; d < MD_; d++) mat[j + 1][d] = row[d];
    }

    #pragma unroll
    for (int c = 0; c < 5; c++) {
        float conv[6];
        #pragma unroll
        for (int t = 0; t < 6; t++) {
            float s = conv_b[c];
            #pragma unroll
            for (int i = 0; i < 6; i++)
                #pragma unroll
                for (int k = 0; k < 3; k++)
                    s += conv_w[c * 18 + i * 3 + k] * mat[i][t + k];
            conv[t] = fmaxf(s, 0.f);
        }
        #pragma unroll
        for (int t = 0; t < 4; t++)
            g_meta[(size_t)b * 20 + c * 4 + t] =
                fmaxf(fmaxf(conv[t], conv[t + 1]), conv[t + 2]);
    }

    float cv[6], s = 0.f;
    #pragma unroll
    for (int c = 0; c < 6; c++) { cv[c] = credit[b * 6 + c]; s += cv[c]; }
    float invs = (s > 0.f) ? (1.0f / s) : 0.f;
    #pragma unroll
    for (int c = 0; c < 6; c++)
        g_bias[(size_t)b * 6 + c] = (s > 0.f) ? cv[c] * invs : (1.0f / 6.0f);
}

// ---------------- kernel 3: LN1, output rounded to tf32, K-padded ----------
__global__ void ln1_kernel(const float* __restrict__ encode,
                           const float* __restrict__ g1,
                           const float* __restrict__ b1) {
    int row = blockIdx.x;
    int tid = threadIdx.x;              // 0..127
    int lane = tid & 31, wid = tid >> 5;

    float4 x = ((const float4*)(encode + (size_t)row * H_))[tid];
    float mv = (tid < 20) ? g_meta[(size_t)row * 20 + tid] : 0.f;
    float s  = x.x + x.y + x.z + x.w + mv;
    float sq = x.x * x.x + x.y * x.y + x.z * x.z + x.w * x.w + mv * mv;

    #pragma unroll
    for (int o = 16; o > 0; o >>= 1) {
        s  += __shfl_down_sync(0xffffffffu, s, o);
        sq += __shfl_down_sync(0xffffffffu, sq, o);
    }
    __shared__ float rs[4], rq[4], st[2];
    if (lane == 0) { rs[wid] = s; rq[wid] = sq; }
    __syncthreads();
    if (tid == 0) {
        float S = rs[0] + rs[1] + rs[2] + rs[3];
        float Q = rq[0] + rq[1] + rq[2] + rq[3];
        float mean = S / (float)KIN;
        float var  = Q / (float)KIN - mean * mean;
        st[0] = mean;
        st[1] = rsqrtf(var + EPS_);
    }
    __syncthreads();
    float mean = st[0], rstd = st[1];

    float* xo = g_xn + (size_t)row * KP;
    float4 gg = ((const float4*)g1)[tid];
    float4 bb = ((const float4*)b1)[tid];
    float4 o;
    o.x = rnd_tf32((x.x - mean) * rstd * gg.x + bb.x);
    o.y = rnd_tf32((x.y - mean) * rstd * gg.y + bb.y);
    o.z = rnd_tf32((x.z - mean) * rstd * gg.z + bb.z);
    o.w = rnd_tf32((x.w - mean) * rstd * gg.w + bb.w);
    ((float4*)xo)[tid] = o;
    if (tid < 20) {
        int k = H_ + tid;
        xo[k] = rnd_tf32((mv - mean) * rstd * g1[k] + b1[k]);
    }
    if (tid < KP - KIN) xo[KIN + tid] = 0.f;
}

// ---------------- kernel 4: pad + tf32-round mlp1_w -> [1024][544] ---------
__global__ void w1pad_kernel(const float* __restrict__ w1) {
    int idx = blockIdx.x * blockDim.x + threadIdx.x;
    if (idx >= CD_ * KP) return;
    int k = idx % KP;
    int n = idx / KP;
    g_w1p[idx] = (k < KIN) ? rnd_tf32(w1[(size_t)n * KIN + k]) : 0.f;
}

// ---------------- kernel 5: tf32 mma.sync GEMM1 + bias + ReLU --------------
// C[B,1024] = relu(Xn[B,544] @ W1p[1024,544]^T + b1)
// CTA tile 128x128, BK=32, 8 warps as 4(m) x 2(n); warp tile 32x64.
#define BK      32
#define LDSRO   36                    // row stride in floats (BK + 4 pad)
#define A_FLTS  (128 * LDSRO)         // 4608 floats = 18432 B
#define STG_FLT (2 * A_FLTS)          // A + B per stage
#define NCHUNK  17

extern __shared__ __align__(128) float smem_f[];

__device__ __forceinline__ void load_chunk_g(uint32_t sbase, int st, int c,
                                             int m0, int n0, int tid) {
    uint32_t a_s = sbase + st * (STG_FLT * 4);
    uint32_t b_s = a_s + A_FLTS * 4;
    const float* Ag = g_xn  + (size_t)m0 * KP + c * BK;
    const float* Bg = g_w1p + (size_t)n0 * KP + c * BK;
    #pragma unroll
    for (int t = 0; t < 4; t++) {
        int u = tid + t * 256;
        int row = u >> 3, seg = u & 7;          // seg: 4-float group within BK
        cp_async16(a_s + (row * LDSRO + seg * 4) * 4, Ag + (size_t)row * KP + seg * 4);
    }
    #pragma unroll
    for (int t = 0; t < 4; t++) {
        int u = tid + t * 256;
        int row = u >> 3, seg = u & 7;
        cp_async16(b_s + (row * LDSRO + seg * 4) * 4, Bg + (size_t)row * KP + seg * 4);
    }
    cp_commit();
}

__global__ __launch_bounds__(256, 1) void gemm1_mma_kernel(const float* __restrict__ b1) {
    const int tid  = threadIdx.x;
    const int warp = tid >> 5;
    const int lane = tid & 31;
    const int gid  = lane >> 2;          // 0..7
    const int tig  = lane & 3;           // 0..3
    const int wm   = warp >> 1;          // 0..3  (m)
    const int wn   = warp & 1;           // 0..1  (n)
    const int n0   = blockIdx.x * 128;
    const int m0   = blockIdx.y * 128;
    uint32_t sbase = smem_u32(smem_f);

    float acc[2][8][4];
    #pragma unroll
    for (int mt = 0; mt < 2; mt++)
        #pragma unroll
        for (int nt = 0; nt < 8; nt++)
            #pragma unroll
            for (int r = 0; r < 4; r++) acc[mt][nt][r] = 0.f;

    load_chunk_g(sbase, 0, 0, m0, n0, tid);

    for (int c = 0; c < NCHUNK; c++) {
        if (c + 1 < NCHUNK) {
            load_chunk_g(sbase, (c + 1) & 1, c + 1, m0, n0, tid);
            cp_wait<1>();
        } else {
            cp_wait<0>();
        }
        __syncthreads();

        const float* As = smem_f + (c & 1) * STG_FLT;
        const float* Bs = As + A_FLTS;
        const float* Arow0 = As + (wm * 32 + gid) * LDSRO + tig;
        const float* Brow0 = Bs + (wn * 64 + gid) * LDSRO + tig;

        #pragma unroll
        for (int ks = 0; ks < 4; ks++) {
            const int k = ks * 8;
            uint32_t af[2][4], bf[8][2];
            #pragma unroll
            for (int mt = 0; mt < 2; mt++) {
                const float* p = Arow0 + mt * 16 * LDSRO + k;
                af[mt][0] = __float_as_uint(p[0]);
                af[mt][1] = __float_as_uint(p[8 * LDSRO]);
                af[mt][2] = __float_as_uint(p[4]);
                af[mt][3] = __float_as_uint(p[8 * LDSRO + 4]);
            }
            #pragma unroll
            for (int nt = 0; nt < 8; nt++) {
                const float* p = Brow0 + nt * 8 * LDSRO + k;
                bf[nt][0] = __float_as_uint(p[0]);
                bf[nt][1] = __float_as_uint(p[4]);
            }
            #pragma unroll
            for (int mt = 0; mt < 2; mt++)
                #pragma unroll
                for (int nt = 0; nt < 8; nt++)
                    mma_tf32(acc[mt][nt], af[mt], bf[nt]);
        }
        __syncthreads();
    }

    // ---- epilogue: bias + ReLU, float2 stores (full 32B sectors) ----
    #pragma unroll
    for (int nt = 0; nt < 8; nt++) {
        int col = n0 + wn * 64 + nt * 8 + tig * 2;
        float bl0 = __ldg(b1 + col);
        float bl1 = __ldg(b1 + col + 1);
        #pragma unroll
        for (int mt = 0; mt < 2; mt++) {
            int rowa = m0 + wm * 32 + mt * 16 + gid;
            float2 v0, v1;
            v0.x = fmaxf(acc[mt][nt][0] + bl0, 0.f);
            v0.y = fmaxf(acc[mt][nt][1] + bl1, 0.f);
            v1.x = fmaxf(acc[mt][nt][2] + bl0, 0.f);
            v1.y = fmaxf(acc[mt][nt][3] + bl1, 0.f);
            *(float2*)(g_feat + (size_t)rowa * CD_ + col)       = v0;
            *(float2*)(g_feat + (size_t)(rowa + 8) * CD_ + col) = v1;
        }
    }
}

// ---------------- kernel 6: LN2 + out GEMM + out_b + biases ----------------
#define FROWS 8
__global__ __launch_bounds__(256) void final_kernel(const float* __restrict__ ln2g,
                                                    const float* __restrict__ ln2b,
                                                    const float* __restrict__ out_w,
                                                    const float* __restrict__ out_b,
                                                    float* __restrict__ out) {
    const int tid = threadIdx.x;
    const int lane = tid & 31, wid = tid >> 5;
    const int k0 = tid * 4;

    float4 gg = ((const float4*)ln2g)[tid];
    float4 bb = ((const float4*)ln2b)[tid];
    float wreg[6][4];
    #pragma unroll
    for (int c = 0; c < 6; c++) {
        float4 w = *(const float4*)(out_w + (size_t)c * CD_ + k0);
        wreg[c][0] = w.x; wreg[c][1] = w.y; wreg[c][2] = w.z; wreg[c][3] = w.w;
    }

    __shared__ float rs[8], rq[8], st[2], accs[8][6];

    int row0 = blockIdx.x * FROWS;
    for (int r = 0; r < FROWS; r++) {
        int row = row0 + r;
        float4 xv = ((const float4*)(g_feat + (size_t)row * CD_))[tid];
        float s  = xv.x + xv.y + xv.z + xv.w;
        float sq = xv.x * xv.x + xv.y * xv.y + xv.z * xv.z + xv.w * xv.w;
        #pragma unroll
        for (int o = 16; o > 0; o >>= 1) {
            s  += __shfl_down_sync(0xffffffffu, s, o);
            sq += __shfl_down_sync(0xffffffffu, sq, o);
        }
        if (lane == 0) { rs[wid] = s; rq[wid] = sq; }
        __syncthreads();
        if (tid == 0) {
            float S = 0.f, Q = 0.f;
            #pragma unroll
            for (int w = 0; w < 8; w++) { S += rs[w]; Q += rq[w]; }
            float mean = S / (float)CD_;
            float var  = Q / (float)CD_ - mean * mean;
            st[0] = mean;
            st[1] = rsqrtf(var + EPS_);
        }
        __syncthreads();
        float mean = st[0], rstd = st[1];

        float xn[4];
        xn[0] = (xv.x - mean) * rstd * gg.x + bb.x;
        xn[1] = (xv.y - mean) * rstd * gg.y + bb.y;
        xn[2] = (xv.z - mean) * rstd * gg.z + bb.z;
        xn[3] = (xv.w - mean) * rstd * gg.w + bb.w;

        float a[6] = {0.f, 0.f, 0.f, 0.f, 0.f, 0.f};
        #pragma unroll
        for (int j = 0; j < 4; j++)
            #pragma unroll
            for (int c = 0; c < 6; c++)
                a[c] += xn[j] * wreg[c][j];

        #pragma unroll
        for (int o = 16; o > 0; o >>= 1)
            #pragma unroll
            for (int c = 0; c < 6; c++)
                a[c] += __shfl_down_sync(0xffffffffu, a[c], o);
        if (lane == 0) {
            #pragma unroll
            for (int c = 0; c < 6; c++) accs[wid][c] = a[c];
        }
        __syncthreads();
        if (tid < 6) {
            float t = 0.f;
            #pragma unroll
            for (int w = 0; w < 8; w++) t += accs[w][tid];
            out[(size_t)row * 6 + tid] = t + out_b[tid] + g_bias[(size_t)row * 6 + tid];
        }
        __syncthreads();
    }
}

// ---------------- launch ---------------------------------------------------
extern "C" void kernel_launch(void* const* d_in, const int* in_sizes, int n_in,
                              void* d_out, int out_size) {
    const float* encode     = (const float*)d_in[0];
    const float* credit_vec = (const float*)d_in[1];
    const float* meta_table = (const float*)d_in[2];
    const float* conv_w     = (const float*)d_in[3];
    const float* conv_b     = (const float*)d_in[4];
    const float* ln1_g      = (const float*)d_in[5];
    const float* ln1_b      = (const float*)d_in[6];
    const float* mlp1_w     = (const float*)d_in[7];
    const float* mlp1_b     = (const float*)d_in[8];
    const float* ln2_g      = (const float*)d_in[9];
    const float* ln2_b      = (const float*)d_in[10];
    const float* out_w      = (const float*)d_in[11];
    const float* out_b      = (const float*)d_in[12];
    const int*   meta_ids   = (const int*)d_in[13];
    const int*   cat_ids    = (const int*)d_in[14];
    const int*   cat_seg    = (const int*)d_in[15];
    float*       out        = (float*)d_out;

    const int smem_bytes = 2 * STG_FLT * 4;   // 73728 B
    cudaFuncSetAttribute(gemm1_mma_kernel,
                         cudaFuncAttributeMaxDynamicSharedMemorySize, smem_bytes);

    zero_kernel<<<512, 256>>>();
    seg_kernel<<<NCAT_ / 256, 256>>>(meta_table, cat_ids, cat_seg);
    meta_kernel<<<B_ / 256, 256>>>(meta_table, credit_vec, conv_w, conv_b, meta_ids);
    ln1_kernel<<<B_, 128>>>(encode, ln1_g, ln1_b);
    w1pad_kernel<<<(CD_ * KP + 255) / 256, 256>>>(mlp1_w);
    {
        dim3 grid(CD_ / 128, B_ / 128);
        gemm1_mma_kernel<<<grid, 256, smem_bytes>>>(mlp1_b);
    }
    final_kernel<<<B_ / FROWS, 256>>>(ln2_g, ln2_b, out_w, out_b, out);
}

// round 9
// speedup vs baseline: 4.3118x; 1.2141x over previous
#include <cuda_runtime.h>
#include <cstdint>

// ---------------- problem constants (pinned by the dataset) ----------------
#define B_    32768
#define H_    512
#define MD_   8
#define CD_   1024
#define KIN   532          // H + 20
#define KP    544          // KIN padded to 17 * 32
#define NCAT_ 262144
#define EPS_  1e-6f

// ---------------- scratch (static device allocations only) -----------------
__device__ __align__(128) float g_sums[B_ * MD_];
__device__ float g_counts[B_];
__device__ float g_meta[B_ * 20];
__device__ float g_bias[B_ * 6];
__device__ __align__(128) float g_xn[(size_t)B_ * KP];    // LN1 output, tf32-rounded, padded
__device__ __align__(128) float g_w1p[CD_ * KP];          // mlp1_w [1024][544] tf32-rounded, padded
__device__ __align__(128) float g_acc[(size_t)B_ * 8];    // per-row {p[6], sum, sumsq}
__device__ float g_wp[6 * CD_];                           // out_w * ln2_g
__device__ float g_S[6];                                  // row sums of g_wp
__device__ float g_T[6];                                  // out_w @ ln2_b

// ---------------- PTX helpers (baseline ISA only, no 'a' features) ---------
__device__ __forceinline__ uint32_t smem_u32(const void* p) {
    uint32_t a;
    asm("{ .reg .u64 t; cvta.to.shared.u64 t, %1; cvt.u32.u64 %0, t; }" : "=r"(a) : "l"(p));
    return a;
}
__device__ __forceinline__ float rnd_tf32(float x) {
    float o;
    asm("cvt.rna.tf32.f32 %0, %1;" : "=f"(o) : "f"(x));
    return o;
}
__device__ __forceinline__ void cp_async16(uint32_t saddr, const void* gaddr) {
    asm volatile("cp.async.cg.shared.global [%0], [%1], 16;" :: "r"(saddr), "l"(gaddr));
}
__device__ __forceinline__ void cp_commit() {
    asm volatile("cp.async.commit_group;");
}
template <int N>
__device__ __forceinline__ void cp_wait() {
    asm volatile("cp.async.wait_group %0;" :: "n"(N) : "memory");
}
__device__ __forceinline__ void mma_tf32(float* c, const uint32_t* a, const uint32_t* b) {
    asm volatile(
        "mma.sync.aligned.m16n8k8.row.col.f32.tf32.tf32.f32 "
        "{%0,%1,%2,%3}, {%4,%5,%6,%7}, {%8,%9}, {%0,%1,%2,%3};"
        : "+f"(c[0]), "+f"(c[1]), "+f"(c[2]), "+f"(c[3])
        : "r"(a[0]), "r"(a[1]), "r"(a[2]), "r"(a[3]), "r"(b[0]), "r"(b[1]));
}

// ---------------- kernel 0: zero scratch (sums, counts, acc) ---------------
__global__ void zero_kernel() {
    int i = blockIdx.x * blockDim.x + threadIdx.x;
    int stride = gridDim.x * blockDim.x;
    for (int j = i; j < B_ * MD_; j += stride) g_sums[j] = 0.f;
    for (int j = i; j < B_; j += stride)       g_counts[j] = 0.f;
    for (int j = i; j < B_ * 8; j += stride)   g_acc[j] = 0.f;
}

// ---------------- kernel 1: ragged segment sums (run-length compressed) ----
// cat_seg is sorted; each thread folds 8 consecutive entries locally and
// flushes via atomics only at run boundaries (~4x fewer atomics).
__global__ void seg_kernel(const float* __restrict__ table,
                           const int* __restrict__ cat_ids,
                           const int* __restrict__ cat_seg) {
    int t = blockIdx.x * blockDim.x + threadIdx.x;
    int base = t * 8;
    if (base >= NCAT_) return;

    float acc[8];
    int seg = cat_seg[base];
    {
        const float4* t4 = (const float4*)(table + (size_t)cat_ids[base] * MD_);
        float4 a = t4[0], b = t4[1];
        acc[0] = a.x; acc[1] = a.y; acc[2] = a.z; acc[3] = a.w;
        acc[4] = b.x; acc[5] = b.y; acc[6] = b.z; acc[7] = b.w;
    }
    float cnt = 1.f;

    #pragma unroll
    for (int j = 1; j < 8; j++) {
        int s2 = cat_seg[base + j];
        const float4* t4 = (const float4*)(table + (size_t)cat_ids[base + j] * MD_);
        float4 a = t4[0], b = t4[1];
        if (s2 != seg) {
            float* dst = g_sums + (size_t)seg * MD_;
            #pragma unroll
            for (int d = 0; d < 8; d++) atomicAdd(dst + d, acc[d]);
            atomicAdd(&g_counts[seg], cnt);
            seg = s2; cnt = 0.f;
            #pragma unroll
            for (int d = 0; d < 8; d++) acc[d] = 0.f;
        }
        acc[0] += a.x; acc[1] += a.y; acc[2] += a.z; acc[3] += a.w;
        acc[4] += b.x; acc[5] += b.y; acc[6] += b.z; acc[7] += b.w;
        cnt += 1.f;
    }
    float* dst = g_sums + (size_t)seg * MD_;
    #pragma unroll
    for (int d = 0; d < 8; d++) atomicAdd(dst + d, acc[d]);
    atomicAdd(&g_counts[seg], cnt);
}

// ---------------- kernel 2: meta conv/pool features + credit biases --------
__global__ void meta_kernel(const float* __restrict__ table,
                            const float* __restrict__ credit,
                            const float* __restrict__ conv_w,
                            const float* __restrict__ conv_b,
                            const int* __restrict__ meta_ids) {
    int b = blockIdx.x * blockDim.x + threadIdx.x;
    if (b >= B_) return;

    float mat[6][MD_];
    float cnt = fmaxf(g_counts[b], 1.0f);
    float inv = 1.0f / cnt;
    #pragma unroll
    for (int d = 0; d < MD_; d++) mat[0][d] = g_sums[(size_t)b * MD_ + d] * inv;
    #pragma unroll
    for (int j = 0; j < 5; j++) {
        int id = meta_ids[b * 5 + j];
        const float* row = table + (size_t)id * MD_;
        #pragma unroll
        for (int d = 0; d < MD_; d++) mat[j + 1][d] = row[d];
    }

    #pragma unroll
    for (int c = 0; c < 5; c++) {
        float conv[6];
        #pragma unroll
        for (int t = 0; t < 6; t++) {
            float s = conv_b[c];
            #pragma unroll
            for (int i = 0; i < 6; i++)
                #pragma unroll
                for (int k = 0; k < 3; k++)
                    s += conv_w[c * 18 + i * 3 + k] * mat[i][t + k];
            conv[t] = fmaxf(s, 0.f);
        }
        #pragma unroll
        for (int t = 0; t < 4; t++)
            g_meta[(size_t)b * 20 + c * 4 + t] =
                fmaxf(fmaxf(conv[t], conv[t + 1]), conv[t + 2]);
    }

    float cv[6], s = 0.f;
    #pragma unroll
    for (int c = 0; c < 6; c++) { cv[c] = credit[b * 6 + c]; s += cv[c]; }
    float invs = (s > 0.f) ? (1.0f / s) : 0.f;
    #pragma unroll
    for (int c = 0; c < 6; c++)
        g_bias[(size_t)b * 6 + c] = (s > 0.f) ? cv[c] * invs : (1.0f / 6.0f);
}

// ---------------- kernel 3: LN1, output rounded to tf32, K-padded ----------
__global__ void ln1_kernel(const float* __restrict__ encode,
                           const float* __restrict__ g1,
                           const float* __restrict__ b1) {
    int row = blockIdx.x;
    int tid = threadIdx.x;              // 0..127
    int lane = tid & 31, wid = tid >> 5;

    float4 x = ((const float4*)(encode + (size_t)row * H_))[tid];
    float mv = (tid < 20) ? g_meta[(size_t)row * 20 + tid] : 0.f;
    float s  = x.x + x.y + x.z + x.w + mv;
    float sq = x.x * x.x + x.y * x.y + x.z * x.z + x.w * x.w + mv * mv;

    #pragma unroll
    for (int o = 16; o > 0; o >>= 1) {
        s  += __shfl_down_sync(0xffffffffu, s, o);
        sq += __shfl_down_sync(0xffffffffu, sq, o);
    }
    __shared__ float rs[4], rq[4], st[2];
    if (lane == 0) { rs[wid] = s; rq[wid] = sq; }
    __syncthreads();
    if (tid == 0) {
        float S = rs[0] + rs[1] + rs[2] + rs[3];
        float Q = rq[0] + rq[1] + rq[2] + rq[3];
        float mean = S / (float)KIN;
        float var  = Q / (float)KIN - mean * mean;
        st[0] = mean;
        st[1] = rsqrtf(var + EPS_);
    }
    __syncthreads();
    float mean = st[0], rstd = st[1];

    float* xo = g_xn + (size_t)row * KP;
    float4 gg = ((const float4*)g1)[tid];
    float4 bb = ((const float4*)b1)[tid];
    float4 o;
    o.x = rnd_tf32((x.x - mean) * rstd * gg.x + bb.x);
    o.y = rnd_tf32((x.y - mean) * rstd * gg.y + bb.y);
    o.z = rnd_tf32((x.z - mean) * rstd * gg.z + bb.z);
    o.w = rnd_tf32((x.w - mean) * rstd * gg.w + bb.w);
    ((float4*)xo)[tid] = o;
    if (tid < 20) {
        int k = H_ + tid;
        xo[k] = rnd_tf32((mv - mean) * rstd * g1[k] + b1[k]);
    }
    if (tid < KP - KIN) xo[KIN + tid] = 0.f;
}

// ---------------- kernel 4: pad + tf32-round mlp1_w -> [1024][544] ---------
__global__ void w1pad_kernel(const float* __restrict__ w1) {
    int idx = blockIdx.x * blockDim.x + threadIdx.x;
    if (idx >= CD_ * KP) return;
    int k = idx % KP;
    int n = idx / KP;
    g_w1p[idx] = (k < KIN) ? rnd_tf32(w1[(size_t)n * KIN + k]) : 0.f;
}

// ---------------- kernel 4b: W' = out_w * ln2_g ; S = sum W' ; T = out_w@ln2_b
__global__ void prep_kernel(const float* __restrict__ out_w,
                            const float* __restrict__ ln2g,
                            const float* __restrict__ ln2b) {
    int c = blockIdx.x;           // 0..5
    int tid = threadIdx.x;        // 0..255
    int lane = tid & 31, wid = tid >> 5;
    float s = 0.f, t = 0.f;
    for (int k = tid; k < CD_; k += 256) {
        float w  = out_w[c * CD_ + k];
        float wp = w * ln2g[k];
        g_wp[c * CD_ + k] = wp;
        s += wp;
        t += w * ln2b[k];
    }
    #pragma unroll
    for (int o = 16; o > 0; o >>= 1) {
        s += __shfl_down_sync(0xffffffffu, s, o);
        t += __shfl_down_sync(0xffffffffu, t, o);
    }
    __shared__ float rs[8], rt[8];
    if (lane == 0) { rs[wid] = s; rt[wid] = t; }
    __syncthreads();
    if (tid == 0) {
        float S = 0.f, T = 0.f;
        #pragma unroll
        for (int w = 0; w < 8; w++) { S += rs[w]; T += rt[w]; }
        g_S[c] = S; g_T[c] = T;
    }
}

// ---------------- kernel 5: tf32 mma.sync GEMM1 + fused LN2 partials -------
// For each row: p[c] = sum_k W'[c,k]*relu_k, sum = sum relu_k, sumsq = sum relu_k^2
// accumulated into g_acc[row][8] via atomics. No feat materialization.
#define BK      32
#define LDSRO   36                    // row stride in floats (BK + 4 pad)
#define A_FLTS  (128 * LDSRO)         // 4608 floats = 18432 B
#define STG_FLT (2 * A_FLTS)          // A + B per stage
#define NCHUNK  17

extern __shared__ __align__(128) float smem_f[];

__device__ __forceinline__ void load_chunk_g(uint32_t sbase, int st, int c,
                                             int m0, int n0, int tid) {
    uint32_t a_s = sbase + st * (STG_FLT * 4);
    uint32_t b_s = a_s + A_FLTS * 4;
    const float* Ag = g_xn  + (size_t)m0 * KP + c * BK;
    const float* Bg = g_w1p + (size_t)n0 * KP + c * BK;
    #pragma unroll
    for (int t = 0; t < 4; t++) {
        int u = tid + t * 256;
        int row = u >> 3, seg = u & 7;
        cp_async16(a_s + (row * LDSRO + seg * 4) * 4, Ag + (size_t)row * KP + seg * 4);
    }
    #pragma unroll
    for (int t = 0; t < 4; t++) {
        int u = tid + t * 256;
        int row = u >> 3, seg = u & 7;
        cp_async16(b_s + (row * LDSRO + seg * 4) * 4, Bg + (size_t)row * KP + seg * 4);
    }
    cp_commit();
}

__global__ __launch_bounds__(256, 1) void gemm1_mma_kernel(const float* __restrict__ b1) {
    const int tid  = threadIdx.x;
    const int warp = tid >> 5;
    const int lane = tid & 31;
    const int gid  = lane >> 2;          // 0..7
    const int tig  = lane & 3;           // 0..3
    const int wm   = warp >> 1;          // 0..3  (m)
    const int wn   = warp & 1;           // 0..1  (n)
    const int n0   = blockIdx.x * 128;
    const int m0   = blockIdx.y * 128;
    uint32_t sbase = smem_u32(smem_f);

    float acc[2][8][4];
    #pragma unroll
    for (int mt = 0; mt < 2; mt++)
        #pragma unroll
        for (int nt = 0; nt < 8; nt++)
            #pragma unroll
            for (int r = 0; r < 4; r++) acc[mt][nt][r] = 0.f;

    load_chunk_g(sbase, 0, 0, m0, n0, tid);

    for (int c = 0; c < NCHUNK; c++) {
        if (c + 1 < NCHUNK) {
            load_chunk_g(sbase, (c + 1) & 1, c + 1, m0, n0, tid);
            cp_wait<1>();
        } else {
            cp_wait<0>();
        }
        __syncthreads();

        const float* As = smem_f + (c & 1) * STG_FLT;
        const float* Bs = As + A_FLTS;
        const float* Arow0 = As + (wm * 32 + gid) * LDSRO + tig;
        const float* Brow0 = Bs + (wn * 64 + gid) * LDSRO + tig;

        #pragma unroll
        for (int ks = 0; ks < 4; ks++) {
            const int k = ks * 8;
            uint32_t af[2][4], bf[8][2];
            #pragma unroll
            for (int mt = 0; mt < 2; mt++) {
                const float* p = Arow0 + mt * 16 * LDSRO + k;
                af[mt][0] = __float_as_uint(p[0]);
                af[mt][1] = __float_as_uint(p[8 * LDSRO]);
                af[mt][2] = __float_as_uint(p[4]);
                af[mt][3] = __float_as_uint(p[8 * LDSRO + 4]);
            }
            #pragma unroll
            for (int nt = 0; nt < 8; nt++) {
                const float* p = Brow0 + nt * 8 * LDSRO + k;
                bf[nt][0] = __float_as_uint(p[0]);
                bf[nt][1] = __float_as_uint(p[4]);
            }
            #pragma unroll
            for (int mt = 0; mt < 2; mt++)
                #pragma unroll
                for (int nt = 0; nt < 8; nt++)
                    mma_tf32(acc[mt][nt], af[mt], bf[nt]);
        }
        __syncthreads();
    }

    // ---- fused epilogue: relu + per-row LN2/out-GEMM partials ----
    // part[pi][0..5] = p[c], part[pi][6] = sum, part[pi][7] = sumsq
    float part[4][8];
    #pragma unroll
    for (int pi = 0; pi < 4; pi++)
        #pragma unroll
        for (int j = 0; j < 8; j++) part[pi][j] = 0.f;

    #pragma unroll
    for (int nt = 0; nt < 8; nt++) {
        int col = n0 + wn * 64 + nt * 8 + tig * 2;
        float bl0 = __ldg(b1 + col);
        float bl1 = __ldg(b1 + col + 1);
        float w0[6], w1[6];
        #pragma unroll
        for (int c6 = 0; c6 < 6; c6++) {
            w0[c6] = __ldg(g_wp + c6 * CD_ + col);
            w1[c6] = __ldg(g_wp + c6 * CD_ + col + 1);
        }
        #pragma unroll
        for (int mt = 0; mt < 2; mt++) {
            #pragma unroll
            for (int pr = 0; pr < 2; pr++) {
                float v0 = fmaxf(acc[mt][nt][pr * 2 + 0] + bl0, 0.f);
                float v1 = fmaxf(acc[mt][nt][pr * 2 + 1] + bl1, 0.f);
                int pi = mt * 2 + pr;
                part[pi][6] += v0 + v1;
                part[pi][7] += v0 * v0 + v1 * v1;
                #pragma unroll
                for (int c6 = 0; c6 < 6; c6++)
                    part[pi][c6] += v0 * w0[c6] + v1 * w1[c6];
            }
        }
    }

    // reduce across the 4 tig lanes (same rows)
    #pragma unroll
    for (int pi = 0; pi < 4; pi++)
        #pragma unroll
        for (int j = 0; j < 8; j++) {
            part[pi][j] += __shfl_xor_sync(0xffffffffu, part[pi][j], 1);
            part[pi][j] += __shfl_xor_sync(0xffffffffu, part[pi][j], 2);
        }

    if (tig == 0) {
        #pragma unroll
        for (int pi = 0; pi < 4; pi++) {
            int mt = pi >> 1, pr = pi & 1;
            int row = m0 + wm * 32 + mt * 16 + pr * 8 + gid;
            float* dst = g_acc + (size_t)row * 8;
            #pragma unroll
            for (int j = 0; j < 8; j++) atomicAdd(dst + j, part[pi][j]);
        }
    }
}

// ---------------- kernel 6: tiny finalize: LN2 stats + affine + biases -----
__global__ __launch_bounds__(256) void final2_kernel(const float* __restrict__ out_b,
                                                     float* __restrict__ out) {
    int i = blockIdx.x * blockDim.x + threadIdx.x;   // B*6
    if (i >= B_ * 6) return;
    int row = i / 6, c = i % 6;
    const float* a = g_acc + (size_t)row * 8;
    float p = a[c], s = a[6], q = a[7];
    float mu   = s * (1.0f / (float)CD_);
    float var  = q * (1.0f / (float)CD_) - mu * mu;
    float rstd = rsqrtf(var + EPS_);
    out[i] = rstd * p - rstd * mu * g_S[c] + g_T[c] + out_b[c] + g_bias[i];
}

// ---------------- launch ---------------------------------------------------
extern "C" void kernel_launch(void* const* d_in, const int* in_sizes, int n_in,
                              void* d_out, int out_size) {
    const float* encode     = (const float*)d_in[0];
    const float* credit_vec = (const float*)d_in[1];
    const float* meta_table = (const float*)d_in[2];
    const float* conv_w     = (const float*)d_in[3];
    const float* conv_b     = (const float*)d_in[4];
    const float* ln1_g      = (const float*)d_in[5];
    const float* ln1_b      = (const float*)d_in[6];
    const float* mlp1_w     = (const float*)d_in[7];
    const float* mlp1_b     = (const float*)d_in[8];
    const float* ln2_g      = (const float*)d_in[9];
    const float* ln2_b      = (const float*)d_in[10];
    const float* out_w      = (const float*)d_in[11];
    const float* out_b      = (const float*)d_in[12];
    const int*   meta_ids   = (const int*)d_in[13];
    const int*   cat_ids    = (const int*)d_in[14];
    const int*   cat_seg    = (const int*)d_in[15];
    float*       out        = (float*)d_out;

    const int smem_bytes = 2 * STG_FLT * 4;   // 73728 B
    cudaFuncSetAttribute(gemm1_mma_kernel,
                         cudaFuncAttributeMaxDynamicSharedMemorySize, smem_bytes);

    zero_kernel<<<512, 256>>>();
    seg_kernel<<<NCAT_ / 8 / 256, 256>>>(meta_table, cat_ids, cat_seg);
    meta_kernel<<<B_ / 256, 256>>>(meta_table, credit_vec, conv_w, conv_b, meta_ids);
    ln1_kernel<<<B_, 128>>>(encode, ln1_g, ln1_b);
    w1pad_kernel<<<(CD_ * KP + 255) / 256, 256>>>(mlp1_w);
    prep_kernel<<<6, 256>>>(out_w, ln2_g, ln2_b);
    {
        dim3 grid(CD_ / 128, B_ / 128);
        gemm1_mma_kernel<<<grid, 256, smem_bytes>>>(mlp1_b);
    }
    final2_kernel<<<(B_ * 6 + 255) / 256, 256>>>(out_b, out);
}

// round 10
// speedup vs baseline: 5.8163x; 1.3489x over previous
#include <cuda_runtime.h>
#include <cuda_fp16.h>
#include <cstdint>

// ---------------- problem constants (pinned by the dataset) ----------------
#define B_    32768
#define H_    512
#define MD_   8
#define CD_   1024
#define KIN   532          // H + 20
#define KP    544          // KIN padded to 17 * 32
#define NCAT_ 262144
#define EPS_  1e-6f

// ---------------- scratch (static device allocations only) -----------------
__device__ __align__(128) float g_sums[B_ * MD_];
__device__ float g_counts[B_];
__device__ float g_meta[B_ * 20];
__device__ float g_bias[B_ * 6];
__device__ __align__(128) __half g_xn[(size_t)B_ * KP];   // LN1 out, fp16, k-permuted
__device__ __align__(128) __half g_w1p[CD_ * KP];         // mlp1_w fp16, k-permuted
__device__ __align__(128) float g_acc[(size_t)B_ * 8];    // per-row {p[6], sum, sumsq}
__device__ float g_wp[6 * CD_];                           // out_w * ln2_g
__device__ float g_S[6];                                  // row sums of g_wp
__device__ float g_T[6];                                  // out_w @ ln2_b

// k-permutation within each 16-half group: dest pair j holds source pair
// s(j) = (j>>1) + (j&1)*4, so a thread's LDS.64 at halves [4t..4t+3] yields
// source cols {2t, 2t+1, 2t+8, 2t+9} = exactly one mma fragment reg pair.

// ---------------- PTX helpers (baseline ISA only, no 'a' features) ---------
__device__ __forceinline__ uint32_t smem_u32(const void* p) {
    uint32_t a;
    asm("{ .reg .u64 t; cvta.to.shared.u64 t, %1; cvt.u32.u64 %0, t; }" : "=r"(a) : "l"(p));
    return a;
}
__device__ __forceinline__ void cp_async16(uint32_t saddr, const void* gaddr) {
    asm volatile("cp.async.cg.shared.global [%0], [%1], 16;" :: "r"(saddr), "l"(gaddr));
}
__device__ __forceinline__ void cp_commit() {
    asm volatile("cp.async.commit_group;");
}
template <int N>
__device__ __forceinline__ void cp_wait() {
    asm volatile("cp.async.wait_group %0;" :: "n"(N) : "memory");
}
__device__ __forceinline__ void mma_f16(float* c, const uint32_t* a, const uint32_t* b) {
    asm volatile(
        "mma.sync.aligned.m16n8k16.row.col.f32.f16.f16.f32 "
        "{%0,%1,%2,%3}, {%4,%5,%6,%7}, {%8,%9}, {%0,%1,%2,%3};"
        : "+f"(c[0]), "+f"(c[1]), "+f"(c[2]), "+f"(c[3])
        : "r"(a[0]), "r"(a[1]), "r"(a[2]), "r"(a[3]), "r"(b[0]), "r"(b[1]));
}
__device__ __forceinline__ uint32_t pack2h(float a, float b) {
    __half2 h = __floats2half2_rn(a, b);
    return *(uint32_t*)&h;
}

// ---------------- kernel 0: zero scratch (sums, counts, acc) ---------------
__global__ void zero_kernel() {
    int i = blockIdx.x * blockDim.x + threadIdx.x;
    int stride = gridDim.x * blockDim.x;
    for (int j = i; j < B_ * MD_; j += stride) g_sums[j] = 0.f;
    for (int j = i; j < B_; j += stride)       g_counts[j] = 0.f;
    for (int j = i; j < B_ * 8; j += stride)   g_acc[j] = 0.f;
}

// ---------------- kernel 1: ragged segment sums (run-length compressed) ----
__global__ void seg_kernel(const float* __restrict__ table,
                           const int* __restrict__ cat_ids,
                           const int* __restrict__ cat_seg) {
    int t = blockIdx.x * blockDim.x + threadIdx.x;
    int base = t * 8;
    if (base >= NCAT_) return;

    float acc[8];
    int seg = cat_seg[base];
    {
        const float4* t4 = (const float4*)(table + (size_t)cat_ids[base] * MD_);
        float4 a = t4[0], b = t4[1];
        acc[0] = a.x; acc[1] = a.y; acc[2] = a.z; acc[3] = a.w;
        acc[4] = b.x; acc[5] = b.y; acc[6] = b.z; acc[7] = b.w;
    }
    float cnt = 1.f;

    #pragma unroll
    for (int j = 1; j < 8; j++) {
        int s2 = cat_seg[base + j];
        const float4* t4 = (const float4*)(table + (size_t)cat_ids[base + j] * MD_);
        float4 a = t4[0], b = t4[1];
        if (s2 != seg) {
            float* dst = g_sums + (size_t)seg * MD_;
            #pragma unroll
            for (int d = 0; d < 8; d++) atomicAdd(dst + d, acc[d]);
            atomicAdd(&g_counts[seg], cnt);
            seg = s2; cnt = 0.f;
            #pragma unroll
            for (int d = 0; d < 8; d++) acc[d] = 0.f;
        }
        acc[0] += a.x; acc[1] += a.y; acc[2] += a.z; acc[3] += a.w;
        acc[4] += b.x; acc[5] += b.y; acc[6] += b.z; acc[7] += b.w;
        cnt += 1.f;
    }
    float* dst = g_sums + (size_t)seg * MD_;
    #pragma unroll
    for (int d = 0; d < 8; d++) atomicAdd(dst + d, acc[d]);
    atomicAdd(&g_counts[seg], cnt);
}

// ---------------- kernel 2: meta conv/pool features + credit biases --------
__global__ void meta_kernel(const float* __restrict__ table,
                            const float* __restrict__ credit,
                            const float* __restrict__ conv_w,
                            const float* __restrict__ conv_b,
                            const int* __restrict__ meta_ids) {
    int b = blockIdx.x * blockDim.x + threadIdx.x;
    if (b >= B_) return;

    float mat[6][MD_];
    float cnt = fmaxf(g_counts[b], 1.0f);
    float inv = 1.0f / cnt;
    #pragma unroll
    for (int d = 0; d < MD_; d++) mat[0][d] = g_sums[(size_t)b * MD_ + d] * inv;
    #pragma unroll
    for (int j = 0; j < 5; j++) {
        int id = meta_ids[b * 5 + j];
        const float* row = table + (size_t)id * MD_;
        #pragma unroll
        for (int d = 0; d < MD_; d++) mat[j + 1][d] = row[d];
    }

    #pragma unroll
    for (int c = 0; c < 5; c++) {
        float conv[6];
        #pragma unroll
        for (int t = 0; t < 6; t++) {
            float s = conv_b[c];
            #pragma unroll
            for (int i = 0; i < 6; i++)
                #pragma unroll
                for (int k = 0; k < 3; k++)
                    s += conv_w[c * 18 + i * 3 + k] * mat[i][t + k];
            conv[t] = fmaxf(s, 0.f);
        }
        #pragma unroll
        for (int t = 0; t < 4; t++)
            g_meta[(size_t)b * 20 + c * 4 + t] =
                fmaxf(fmaxf(conv[t], conv[t + 1]), conv[t + 2]);
    }

    float cv[6], s = 0.f;
    #pragma unroll
    for (int c = 0; c < 6; c++) { cv[c] = credit[b * 6 + c]; s += cv[c]; }
    float invs = (s > 0.f) ? (1.0f / s) : 0.f;
    #pragma unroll
    for (int c = 0; c < 6; c++)
        g_bias[(size_t)b * 6 + c] = (s > 0.f) ? cv[c] * invs : (1.0f / 6.0f);
}

// ---------------- kernel 3: LN1 -> fp16, k-permuted, padded ----------------
__global__ void ln1_kernel(const float* __restrict__ encode,
                           const float* __restrict__ g1,
                           const float* __restrict__ b1) {
    int row = blockIdx.x;
    int tid = threadIdx.x;              // 0..127
    int lane = tid & 31, wid = tid >> 5;

    __shared__ float buf[KP];
    __shared__ float rs[4], rq[4], st[2];

    float4 x = ((const float4*)(encode + (size_t)row * H_))[tid];
    float mv = (tid < 20) ? g_meta[(size_t)row * 20 + tid] : 0.f;
    float s  = x.x + x.y + x.z + x.w + mv;
    float sq = x.x * x.x + x.y * x.y + x.z * x.z + x.w * x.w + mv * mv;

    #pragma unroll
    for (int o = 16; o > 0; o >>= 1) {
        s  += __shfl_down_sync(0xffffffffu, s, o);
        sq += __shfl_down_sync(0xffffffffu, sq, o);
    }
    if (lane == 0) { rs[wid] = s; rq[wid] = sq; }
    __syncthreads();
    if (tid == 0) {
        float S = rs[0] + rs[1] + rs[2] + rs[3];
        float Q = rq[0] + rq[1] + rq[2] + rq[3];
        float mean = S / (float)KIN;
        float var  = Q / (float)KIN - mean * mean;
        st[0] = mean;
        st[1] = rsqrtf(var + EPS_);
    }
    __syncthreads();
    float mean = st[0], rstd = st[1];

    float4 gg = ((const float4*)g1)[tid];
    float4 bb = ((const float4*)b1)[tid];
    buf[tid * 4 + 0] = (x.x - mean) * rstd * gg.x + bb.x;
    buf[tid * 4 + 1] = (x.y - mean) * rstd * gg.y + bb.y;
    buf[tid * 4 + 2] = (x.z - mean) * rstd * gg.z + bb.z;
    buf[tid * 4 + 3] = (x.w - mean) * rstd * gg.w + bb.w;
    if (tid < 20) {
        int k = H_ + tid;
        buf[k] = (mv - mean) * rstd * g1[k] + b1[k];
    }
    if (tid < KP - KIN) buf[KIN + tid] = 0.f;
    __syncthreads();

    // permuted fp16 pack: dest block bi (4 halves) <- src {p, p+1, p+8, p+9}
    uint2* xo = (uint2*)(g_xn + (size_t)row * KP);
    #pragma unroll
    for (int it = 0; it < 2; it++) {
        int bi = tid + it * 128;
        if (bi < KP / 4) {
            int g = bi >> 2, t = bi & 3;
            int p = g * 16 + t * 2;
            uint2 u;
            u.x = pack2h(buf[p], buf[p + 1]);
            u.y = pack2h(buf[p + 8], buf[p + 9]);
            xo[bi] = u;
        }
    }
}

// ---------------- kernel 4: pad + fp16 + k-permute mlp1_w ------------------
__global__ void w1pad_kernel(const float* __restrict__ w1) {
    int bi = blockIdx.x * blockDim.x + threadIdx.x;   // dest 4-half block
    if (bi >= CD_ * KP / 4) return;
    int n = bi / (KP / 4);
    int r = bi % (KP / 4);
    int g = r >> 2, t = r & 3;
    int p = g * 16 + t * 2;                           // src half index in row
    const float* wrow = w1 + (size_t)n * KIN;
    float v0 = (p + 0 < KIN) ? wrow[p + 0] : 0.f;
    float v1 = (p + 1 < KIN) ? wrow[p + 1] : 0.f;
    float v2 = (p + 8 < KIN) ? wrow[p + 8] : 0.f;
    float v3 = (p + 9 < KIN) ? wrow[p + 9] : 0.f;
    uint2 u;
    u.x = pack2h(v0, v1);
    u.y = pack2h(v2, v3);
    ((uint2*)g_w1p)[bi] = u;
}

// ---------------- kernel 4b: W' = out_w * ln2_g ; S = sum W' ; T = out_w@ln2_b
__global__ void prep_kernel(const float* __restrict__ out_w,
                            const float* __restrict__ ln2g,
                            const float* __restrict__ ln2b) {
    int c = blockIdx.x;           // 0..5
    int tid = threadIdx.x;        // 0..255
    int lane = tid & 31, wid = tid >> 5;
    float s = 0.f, t = 0.f;
    for (int k = tid; k < CD_; k += 256) {
        float w  = out_w[c * CD_ + k];
        float wp = w * ln2g[k];
        g_wp[c * CD_ + k] = wp;
        s += wp;
        t += w * ln2b[k];
    }
    #pragma unroll
    for (int o = 16; o > 0; o >>= 1) {
        s += __shfl_down_sync(0xffffffffu, s, o);
        t += __shfl_down_sync(0xffffffffu, t, o);
    }
    __shared__ float rs[8], rt[8];
    if (lane == 0) { rs[wid] = s; rt[wid] = t; }
    __syncthreads();
    if (tid == 0) {
        float S = 0.f, T = 0.f;
        #pragma unroll
        for (int w = 0; w < 8; w++) { S += rs[w]; T += rt[w]; }
        g_S[c] = S; g_T[c] = T;
    }
}

// ---------------- kernel 5: fp16 mma.sync GEMM1 + fused LN2 partials -------
// CTA tile 128x128, BK=32 halves, 8 warps 4(m)x2(n), warp tile 32x64.
// 3-stage cp.async pipeline; LDS.64 fragment loads via k-permuted layout.
#define BK      32
#define SROW    48                     // halves per smem row (96 B)
#define A_HALFS (128 * SROW)
#define STG_HLF (2 * A_HALFS)          // A + B per stage
#define NSTG    3
#define NCHUNK  17

extern __shared__ __align__(128) __half smem_h[];

__device__ __forceinline__ void load_chunk_h(uint32_t sbase, int st, int c,
                                             int m0, int n0, int tid) {
    uint32_t a_s = sbase + st * (STG_HLF * 2);
    uint32_t b_s = a_s + A_HALFS * 2;
    const __half* Ag = g_xn  + (size_t)m0 * KP + c * BK;
    const __half* Bg = g_w1p + (size_t)n0 * KP + c * BK;
    #pragma unroll
    for (int t = 0; t < 2; t++) {
        int u = tid + t * 256;
        int row = u >> 2, seg = u & 3;          // 16B (8-half) segments
        cp_async16(a_s + (row * SROW + seg * 8) * 2, Ag + (size_t)row * KP + seg * 8);
    }
    #pragma unroll
    for (int t = 0; t < 2; t++) {
        int u = tid + t * 256;
        int row = u >> 2, seg = u & 3;
        cp_async16(b_s + (row * SROW + seg * 8) * 2, Bg + (size_t)row * KP + seg * 8);
    }
    cp_commit();
}

__global__ __launch_bounds__(256, 1) void gemm1_mma_kernel(const float* __restrict__ b1) {
    const int tid  = threadIdx.x;
    const int warp = tid >> 5;
    const int lane = tid & 31;
    const int gid  = lane >> 2;          // 0..7
    const int tig  = lane & 3;           // 0..3
    const int wm   = warp >> 1;          // 0..3  (m)
    const int wn   = warp & 1;           // 0..1  (n)
    const int n0   = blockIdx.x * 128;
    const int m0   = blockIdx.y * 128;
    uint32_t sbase = smem_u32(smem_h);

    float acc[2][8][4];
    #pragma unroll
    for (int mt = 0; mt < 2; mt++)
        #pragma unroll
        for (int nt = 0; nt < 8; nt++)
            #pragma unroll
            for (int r = 0; r < 4; r++) acc[mt][nt][r] = 0.f;

    load_chunk_h(sbase, 0, 0, m0, n0, tid);
    load_chunk_h(sbase, 1, 1, m0, n0, tid);

    for (int c = 0; c < NCHUNK; c++) {
        if (c + 2 < NCHUNK) {
            load_chunk_h(sbase, (c + 2) % NSTG, c + 2, m0, n0, tid);
            cp_wait<2>();
        } else if (c + 1 < NCHUNK) {
            cp_wait<1>();
        } else {
            cp_wait<0>();
        }
        __syncthreads();

        const __half* As = smem_h + (c % NSTG) * STG_HLF;
        const __half* Bs = As + A_HALFS;
        const __half* Arow0 = As + (wm * 32 + gid) * SROW + tig * 4;
        const __half* Brow0 = Bs + (wn * 64 + gid) * SROW + tig * 4;

        #pragma unroll
        for (int ks = 0; ks < 2; ks++) {
            const int k = ks * 16;
            uint32_t af[2][4], bf[8][2];
            #pragma unroll
            for (int mt = 0; mt < 2; mt++) {
                uint2 q0 = *(const uint2*)(Arow0 + mt * 16 * SROW + k);
                uint2 q1 = *(const uint2*)(Arow0 + (mt * 16 + 8) * SROW + k);
                af[mt][0] = q0.x; af[mt][1] = q1.x;
                af[mt][2] = q0.y; af[mt][3] = q1.y;
            }
            #pragma unroll
            for (int nt = 0; nt < 8; nt++) {
                uint2 qb = *(const uint2*)(Brow0 + nt * 8 * SROW + k);
                bf[nt][0] = qb.x; bf[nt][1] = qb.y;
            }
            #pragma unroll
            for (int mt = 0; mt < 2; mt++)
                #pragma unroll
                for (int nt = 0; nt < 8; nt++)
                    mma_f16(acc[mt][nt], af[mt], bf[nt]);
        }
        __syncthreads();
    }

    // ---- fused epilogue: relu + per-row LN2/out-GEMM partials ----
    float part[4][8];
    #pragma unroll
    for (int pi = 0; pi < 4; pi++)
        #pragma unroll
        for (int j = 0; j < 8; j++) part[pi][j] = 0.f;

    #pragma unroll
    for (int nt = 0; nt < 8; nt++) {
        int col = n0 + wn * 64 + nt * 8 + tig * 2;
        float bl0 = __ldg(b1 + col);
        float bl1 = __ldg(b1 + col + 1);
        float w0[6], w1[6];
        #pragma unroll
        for (int c6 = 0; c6 < 6; c6++) {
            w0[c6] = __ldg(g_wp + c6 * CD_ + col);
            w1[c6] = __ldg(g_wp + c6 * CD_ + col + 1);
        }
        #pragma unroll
        for (int mt = 0; mt < 2; mt++) {
            #pragma unroll
            for (int pr = 0; pr < 2; pr++) {
                float v0 = fmaxf(acc[mt][nt][pr * 2 + 0] + bl0, 0.f);
                float v1 = fmaxf(acc[mt][nt][pr * 2 + 1] + bl1, 0.f);
                int pi = mt * 2 + pr;
                part[pi][6] += v0 + v1;
                part[pi][7] += v0 * v0 + v1 * v1;
                #pragma unroll
                for (int c6 = 0; c6 < 6; c6++)
                    part[pi][c6] += v0 * w0[c6] + v1 * w1[c6];
            }
        }
    }

    #pragma unroll
    for (int pi = 0; pi < 4; pi++)
        #pragma unroll
        for (int j = 0; j < 8; j++) {
            part[pi][j] += __shfl_xor_sync(0xffffffffu, part[pi][j], 1);
            part[pi][j] += __shfl_xor_sync(0xffffffffu, part[pi][j], 2);
        }

    if (tig == 0) {
        #pragma unroll
        for (int pi = 0; pi < 4; pi++) {
            int mt = pi >> 1, pr = pi & 1;
            int row = m0 + wm * 32 + mt * 16 + pr * 8 + gid;
            float* dst = g_acc + (size_t)row * 8;
            #pragma unroll
            for (int j = 0; j < 8; j++) atomicAdd(dst + j, part[pi][j]);
        }
    }
}

// ---------------- kernel 6: tiny finalize: LN2 stats + affine + biases -----
__global__ __launch_bounds__(256) void final2_kernel(const float* __restrict__ out_b,
                                                     float* __restrict__ out) {
    int i = blockIdx.x * blockDim.x + threadIdx.x;   // B*6
    if (i >= B_ * 6) return;
    int row = i / 6, c = i % 6;
    const float* a = g_acc + (size_t)row * 8;
    float p = a[c], s = a[6], q = a[7];
    float mu   = s * (1.0f / (float)CD_);
    float var  = q * (1.0f / (float)CD_) - mu * mu;
    float rstd = rsqrtf(var + EPS_);
    out[i] = rstd * p - rstd * mu * g_S[c] + g_T[c] + out_b[c] + g_bias[i];
}

// ---------------- launch ---------------------------------------------------
extern "C" void kernel_launch(void* const* d_in, const int* in_sizes, int n_in,
                              void* d_out, int out_size) {
    const float* encode     = (const float*)d_in[0];
    const float* credit_vec = (const float*)d_in[1];
    const float* meta_table = (const float*)d_in[2];
    const float* conv_w     = (const float*)d_in[3];
    const float* conv_b     = (const float*)d_in[4];
    const float* ln1_g      = (const float*)d_in[5];
    const float* ln1_b      = (const float*)d_in[6];
    const float* mlp1_w     = (const float*)d_in[7];
    const float* mlp1_b     = (const float*)d_in[8];
    const float* ln2_g      = (const float*)d_in[9];
    const float* ln2_b      = (const float*)d_in[10];
    const float* out_w      = (const float*)d_in[11];
    const float* out_b      = (const float*)d_in[12];
    const int*   meta_ids   = (const int*)d_in[13];
    const int*   cat_ids    = (const int*)d_in[14];
    const int*   cat_seg    = (const int*)d_in[15];
    float*       out        = (float*)d_out;

    const int smem_bytes = NSTG * STG_HLF * 2;   // 73728 B
    cudaFuncSetAttribute(gemm1_mma_kernel,
                         cudaFuncAttributeMaxDynamicSharedMemorySize, smem_bytes);

    zero_kernel<<<512, 256>>>();
    seg_kernel<<<NCAT_ / 8 / 256, 256>>>(meta_table, cat_ids, cat_seg);
    meta_kernel<<<B_ / 256, 256>>>(meta_table, credit_vec, conv_w, conv_b, meta_ids);
    ln1_kernel<<<B_, 128>>>(encode, ln1_g, ln1_b);
    w1pad_kernel<<<(CD_ * KP / 4 + 255) / 256, 256>>>(mlp1_w);
    prep_kernel<<<6, 256>>>(out_w, ln2_g, ln2_b);
    {
        dim3 grid(CD_ / 128, B_ / 128);
        gemm1_mma_kernel<<<grid, 256, smem_bytes>>>(mlp1_b);
    }
    final2_kernel<<<(B_ * 6 + 255) / 256, 256>>>(out_b, out);
}

// round 12
// speedup vs baseline: 7.1353x; 1.2268x over previous
#include <cuda_runtime.h>
#include <cuda_fp16.h>
#include <cstdint>

// ---------------- problem constants (pinned by the dataset) ----------------
#define B_    32768
#define H_    512
#define MD_   8
#define CD_   1024
#define KIN   532          // H + 20
#define KP    544          // KIN padded to 17 * 32
#define NCAT_ 262144
#define EPS_  1e-6f

// ---------------- scratch (static device allocations only) -----------------
__device__ __align__(128) float g_sums[B_ * MD_];
__device__ float g_counts[B_];
__device__ float g_meta[B_ * 20];
__device__ float g_bias[B_ * 6];
__device__ __align__(128) __half g_xn[(size_t)B_ * KP];   // LN1 out, fp16, k-permuted
__device__ __align__(128) __half g_w1p[CD_ * KP];         // mlp1_w fp16, k-permuted
__device__ __align__(128) float g_acc[(size_t)B_ * 8];    // per-row {p[6], sum, sumsq}
__device__ float g_wp[6 * CD_];                           // out_w * ln2_g
__device__ float g_S[6];                                  // row sums of g_wp
__device__ float g_T[6];                                  // out_w @ ln2_b

// k-permutation within each 16-half group: dest 4-half block b holds source
// halves {2b, 2b+1, 2b+8, 2b+9}; a thread's LDS.64 yields one mma fragment pair.

// ---------------- PTX helpers (baseline ISA only, no 'a' features) ---------
__device__ __forceinline__ uint32_t smem_u32(const void* p) {
    uint32_t a;
    asm("{ .reg .u64 t; cvta.to.shared.u64 t, %1; cvt.u32.u64 %0, t; }" : "=r"(a) : "l"(p));
    return a;
}
__device__ __forceinline__ void cp_async16(uint32_t saddr, const void* gaddr) {
    asm volatile("cp.async.cg.shared.global [%0], [%1], 16;" :: "r"(saddr), "l"(gaddr));
}
__device__ __forceinline__ void cp_commit() {
    asm volatile("cp.async.commit_group;");
}
template <int N>
__device__ __forceinline__ void cp_wait() {
    asm volatile("cp.async.wait_group %0;" :: "n"(N) : "memory");
}
__device__ __forceinline__ void mma_f16(float* c, const uint32_t* a, const uint32_t* b) {
    asm volatile(
        "mma.sync.aligned.m16n8k16.row.col.f32.f16.f16.f32 "
        "{%0,%1,%2,%3}, {%4,%5,%6,%7}, {%8,%9}, {%0,%1,%2,%3};"
        : "+f"(c[0]), "+f"(c[1]), "+f"(c[2]), "+f"(c[3])
        : "r"(a[0]), "r"(a[1]), "r"(a[2]), "r"(a[3]), "r"(b[0]), "r"(b[1]));
}
__device__ __forceinline__ uint32_t pack2h(float a, float b) {
    __half2 h = __floats2half2_rn(a, b);
    return *(uint32_t*)&h;
}

// ---------------- kernel 0: zero scratch (sums, counts, acc) ---------------
__global__ void zero_kernel() {
    int i = blockIdx.x * blockDim.x + threadIdx.x;
    int stride = gridDim.x * blockDim.x;
    for (int j = i; j < B_ * MD_; j += stride) g_sums[j] = 0.f;
    for (int j = i; j < B_; j += stride)       g_counts[j] = 0.f;
    for (int j = i; j < B_ * 8; j += stride)   g_acc[j] = 0.f;
}

// ---------------- kernel 1: ragged segment sums (run-length compressed) ----
__global__ void seg_kernel(const float* __restrict__ table,
                           const int* __restrict__ cat_ids,
                           const int* __restrict__ cat_seg) {
    int t = blockIdx.x * blockDim.x + threadIdx.x;
    int base = t * 8;
    if (base >= NCAT_) return;

    float acc[8];
    int seg = cat_seg[base];
    {
        const float4* t4 = (const float4*)(table + (size_t)cat_ids[base] * MD_);
        float4 a = t4[0], b = t4[1];
        acc[0] = a.x; acc[1] = a.y; acc[2] = a.z; acc[3] = a.w;
        acc[4] = b.x; acc[5] = b.y; acc[6] = b.z; acc[7] = b.w;
    }
    float cnt = 1.f;

    #pragma unroll
    for (int j = 1; j < 8; j++) {
        int s2 = cat_seg[base + j];
        const float4* t4 = (const float4*)(table + (size_t)cat_ids[base + j] * MD_);
        float4 a = t4[0], b = t4[1];
        if (s2 != seg) {
            float* dst = g_sums + (size_t)seg * MD_;
            #pragma unroll
            for (int d = 0; d < 8; d++) atomicAdd(dst + d, acc[d]);
            atomicAdd(&g_counts[seg], cnt);
            seg = s2; cnt = 0.f;
            #pragma unroll
            for (int d = 0; d < 8; d++) acc[d] = 0.f;
        }
        acc[0] += a.x; acc[1] += a.y; acc[2] += a.z; acc[3] += a.w;
        acc[4] += b.x; acc[5] += b.y; acc[6] += b.z; acc[7] += b.w;
        cnt += 1.f;
    }
    float* dst = g_sums + (size_t)seg * MD_;
    #pragma unroll
    for (int d = 0; d < 8; d++) atomicAdd(dst + d, acc[d]);
    atomicAdd(&g_counts[seg], cnt);
}

// ---------------- kernel 2: meta conv/pool features + credit biases --------
__global__ void meta_kernel(const float* __restrict__ table,
                            const float* __restrict__ credit,
                            const float* __restrict__ conv_w,
                            const float* __restrict__ conv_b,
                            const int* __restrict__ meta_ids) {
    int b = blockIdx.x * blockDim.x + threadIdx.x;
    if (b >= B_) return;

    float mat[6][MD_];
    float cnt = fmaxf(g_counts[b], 1.0f);
    float inv = 1.0f / cnt;
    #pragma unroll
    for (int d = 0; d < MD_; d++) mat[0][d] = g_sums[(size_t)b * MD_ + d] * inv;
    #pragma unroll
    for (int j = 0; j < 5; j++) {
        int id = meta_ids[b * 5 + j];
        const float* row = table + (size_t)id * MD_;
        #pragma unroll
        for (int d = 0; d < MD_; d++) mat[j + 1][d] = row[d];
    }

    #pragma unroll
    for (int c = 0; c < 5; c++) {
        float conv[6];
        #pragma unroll
        for (int t = 0; t < 6; t++) {
            float s = conv_b[c];
            #pragma unroll
            for (int i = 0; i < 6; i++)
                #pragma unroll
                for (int k = 0; k < 3; k++)
                    s += conv_w[c * 18 + i * 3 + k] * mat[i][t + k];
            conv[t] = fmaxf(s, 0.f);
        }
        #pragma unroll
        for (int t = 0; t < 4; t++)
            g_meta[(size_t)b * 20 + c * 4 + t] =
                fmaxf(fmaxf(conv[t], conv[t + 1]), conv[t + 2]);
    }

    float cv[6], s = 0.f;
    #pragma unroll
    for (int c = 0; c < 6; c++) { cv[c] = credit[b * 6 + c]; s += cv[c]; }
    float invs = (s > 0.f) ? (1.0f / s) : 0.f;
    #pragma unroll
    for (int c = 0; c < 6; c++)
        g_bias[(size_t)b * 6 + c] = (s > 0.f) ? cv[c] * invs : (1.0f / 6.0f);
}

// ---------------- kernel 3: LN1 -> fp16, k-permuted via shfl exchange ------
__global__ void ln1_kernel(const float* __restrict__ encode,
                           const float* __restrict__ g1,
                           const float* __restrict__ b1) {
    int row = blockIdx.x;
    int tid = threadIdx.x;              // 0..127
    int lane = tid & 31, wid = tid >> 5;

    __shared__ float rs[4], rq[4], st[2];
    __shared__ float tailbuf[32];

    float4 x = ((const float4*)(encode + (size_t)row * H_))[tid];
    float mv = (tid < 20) ? g_meta[(size_t)row * 20 + tid] : 0.f;
    float s  = x.x + x.y + x.z + x.w + mv;
    float sq = x.x * x.x + x.y * x.y + x.z * x.z + x.w * x.w + mv * mv;

    #pragma unroll
    for (int o = 16; o > 0; o >>= 1) {
        s  += __shfl_down_sync(0xffffffffu, s, o);
        sq += __shfl_down_sync(0xffffffffu, sq, o);
    }
    if (lane == 0) { rs[wid] = s; rq[wid] = sq; }
    __syncthreads();
    if (tid == 0) {
        float S = rs[0] + rs[1] + rs[2] + rs[3];
        float Q = rq[0] + rq[1] + rq[2] + rq[3];
        float mean = S / (float)KIN;
        float var  = Q / (float)KIN - mean * mean;
        st[0] = mean;
        st[1] = rsqrtf(var + EPS_);
    }
    __syncthreads();
    float mean = st[0], rstd = st[1];

    // normalize own 4 values (halves 4*tid .. 4*tid+3)
    float4 gg = ((const float4*)g1)[tid];
    float4 bb = ((const float4*)b1)[tid];
    float v0 = (x.x - mean) * rstd * gg.x + bb.x;
    float v1 = (x.y - mean) * rstd * gg.y + bb.y;
    float v2 = (x.z - mean) * rstd * gg.z + bb.z;
    float v3 = (x.w - mean) * rstd * gg.w + bb.w;

    uint32_t u0 = pack2h(v0, v1);
    uint32_t u1 = pack2h(v2, v3);
    uint32_t pu0 = __shfl_xor_sync(0xffffffffu, u0, 2);
    uint32_t pu1 = __shfl_xor_sync(0xffffffffu, u1, 2);

    // permuted write: group g = tid>>2, t = tid&3
    // t in {0,1}: block 4g+2t = {u0, pu0};  t in {2,3}: block 4g+2t-3 = {pu1, u1}
    uint2* xo = (uint2*)(g_xn + (size_t)row * KP);
    int g = tid >> 2, t = tid & 3;
    uint2 u;
    int bi;
    if (t < 2) { u.x = u0;  u.y = pu0; bi = g * 4 + 2 * t; }
    else       { u.x = pu1; u.y = u1;  bi = g * 4 + 2 * t - 3; }
    xo[bi] = u;

    // tail: halves 512..543 (meta 20 + pad 12) via tiny smem buffer
    if (tid < 32) {
        float tv = 0.f;
        if (tid < 20) {
            int k = H_ + tid;
            tv = (mv - mean) * rstd * g1[k] + b1[k];
        }
        tailbuf[tid] = tv;
    }
    __syncthreads();
    if (tid < 8) {
        int gg2 = tid >> 2, b = tid & 3;          // groups 32,33
        int base = gg2 * 16 + 2 * b;
        uint2 ut;
        ut.x = pack2h(tailbuf[base],     tailbuf[base + 1]);
        ut.y = pack2h(tailbuf[base + 8], tailbuf[base + 9]);
        xo[128 + gg2 * 4 + b] = ut;
    }
}

// ---------------- kernel 4: pad + fp16 + k-permute mlp1_w ------------------
__global__ void w1pad_kernel(const float* __restrict__ w1) {
    int bi = blockIdx.x * blockDim.x + threadIdx.x;   // dest 4-half block
    if (bi >= CD_ * KP / 4) return;
    int n = bi / (KP / 4);
    int r = bi % (KP / 4);
    int g = r >> 2, t = r & 3;
    int p = g * 16 + t * 2;                           // src half index in row
    const float* wrow = w1 + (size_t)n * KIN;
    float v0 = (p + 0 < KIN) ? wrow[p + 0] : 0.f;
    float v1 = (p + 1 < KIN) ? wrow[p + 1] : 0.f;
    float v2 = (p + 8 < KIN) ? wrow[p + 8] : 0.f;
    float v3 = (p + 9 < KIN) ? wrow[p + 9] : 0.f;
    uint2 u;
    u.x = pack2h(v0, v1);
    u.y = pack2h(v2, v3);
    ((uint2*)g_w1p)[bi] = u;
}

// ---------------- kernel 4b: W' = out_w * ln2_g ; S = sum W' ; T = out_w@ln2_b
__global__ void prep_kernel(const float* __restrict__ out_w,
                            const float* __restrict__ ln2g,
                            const float* __restrict__ ln2b) {
    int c = blockIdx.x;           // 0..5
    int tid = threadIdx.x;        // 0..255
    int lane = tid & 31, wid = tid >> 5;
    float s = 0.f, t = 0.f;
    for (int k = tid; k < CD_; k += 256) {
        float w  = out_w[c * CD_ + k];
        float wp = w * ln2g[k];
        g_wp[c * CD_ + k] = wp;
        s += wp;
        t += w * ln2b[k];
    }
    #pragma unroll
    for (int o = 16; o > 0; o >>= 1) {
        s += __shfl_down_sync(0xffffffffu, s, o);
        t += __shfl_down_sync(0xffffffffu, t, o);
    }
    __shared__ float rs[8], rt[8];
    if (lane == 0) { rs[wid] = s; rt[wid] = t; }
    __syncthreads();
    if (tid == 0) {
        float S = 0.f, T = 0.f;
        #pragma unroll
        for (int w = 0; w < 8; w++) { S += rs[w]; T += rt[w]; }
        g_S[c] = S; g_T[c] = T;
    }
}

// ---------------- kernel 5: fp16 mma.sync GEMM1 + fused LN2 partials -------
// CTA tile 128x128, BK=32 halves, 8 warps 4(m)x2(n), warp tile 32x64.
// 4-stage cp.async pipeline, 2 CTAs/SM for cross-CTA latency hiding.
#define BK      32
#define SROW    48                     // halves per smem row (96 B)
#define A_HALFS (128 * SROW)
#define STG_HLF (2 * A_HALFS)          // A + B per stage (24576 B)
#define NSTG    4
#define NCHUNK  17

extern __shared__ __align__(128) __half smem_h[];

__device__ __forceinline__ void load_chunk_h(uint32_t sbase, int st, int c,
                                             int m0, int n0, int tid) {
    uint32_t a_s = sbase + st * (STG_HLF * 2);
    uint32_t b_s = a_s + A_HALFS * 2;
    const __half* Ag = g_xn  + (size_t)m0 * KP + c * BK;
    const __half* Bg = g_w1p + (size_t)n0 * KP + c * BK;
    #pragma unroll
    for (int t = 0; t < 2; t++) {
        int u = tid + t * 256;
        int row = u >> 2, seg = u & 3;          // 16B (8-half) segments
        cp_async16(a_s + (row * SROW + seg * 8) * 2, Ag + (size_t)row * KP + seg * 8);
    }
    #pragma unroll
    for (int t = 0; t < 2; t++) {
        int u = tid + t * 256;
        int row = u >> 2, seg = u & 3;
        cp_async16(b_s + (row * SROW + seg * 8) * 2, Bg + (size_t)row * KP + seg * 8);
    }
    cp_commit();
}

__global__ __launch_bounds__(256, 2) void gemm1_mma_kernel(const float* __restrict__ b1) {
    const int tid  = threadIdx.x;
    const int warp = tid >> 5;
    const int lane = tid & 31;
    const int gid  = lane >> 2;          // 0..7
    const int tig  = lane & 3;           // 0..3
    const int wm   = warp >> 1;          // 0..3  (m)
    const int wn   = warp & 1;           // 0..1  (n)
    const int n0   = blockIdx.x * 128;
    const int m0   = blockIdx.y * 128;
    uint32_t sbase = smem_u32(smem_h);

    float acc[2][8][4];
    #pragma unroll
    for (int mt = 0; mt < 2; mt++)
        #pragma unroll
        for (int nt = 0; nt < 8; nt++)
            #pragma unroll
            for (int r = 0; r < 4; r++) acc[mt][nt][r] = 0.f;

    load_chunk_h(sbase, 0, 0, m0, n0, tid);
    load_chunk_h(sbase, 1, 1, m0, n0, tid);
    load_chunk_h(sbase, 2, 2, m0, n0, tid);

    for (int c = 0; c < NCHUNK; c++) {
        if (c + 3 < NCHUNK) {
            load_chunk_h(sbase, (c + 3) & (NSTG - 1), c + 3, m0, n0, tid);
            cp_wait<3>();
        } else if (c + 2 < NCHUNK) {
            cp_wait<2>();
        } else if (c + 1 < NCHUNK) {
            cp_wait<1>();
        } else {
            cp_wait<0>();
        }
        __syncthreads();

        const __half* As = smem_h + (c & (NSTG - 1)) * STG_HLF;
        const __half* Bs = As + A_HALFS;
        const __half* Arow0 = As + (wm * 32 + gid) * SROW + tig * 4;
        const __half* Brow0 = Bs + (wn * 64 + gid) * SROW + tig * 4;

        #pragma unroll
        for (int ks = 0; ks < 2; ks++) {
            const int k = ks * 16;
            uint32_t af[2][4], bf[8][2];
            #pragma unroll
            for (int mt = 0; mt < 2; mt++) {
                uint2 q0 = *(const uint2*)(Arow0 + mt * 16 * SROW + k);
                uint2 q1 = *(const uint2*)(Arow0 + (mt * 16 + 8) * SROW + k);
                af[mt][0] = q0.x; af[mt][1] = q1.x;
                af[mt][2] = q0.y; af[mt][3] = q1.y;
            }
            #pragma unroll
            for (int nt = 0; nt < 8; nt++) {
                uint2 qb = *(const uint2*)(Brow0 + nt * 8 * SROW + k);
                bf[nt][0] = qb.x; bf[nt][1] = qb.y;
            }
            #pragma unroll
            for (int mt = 0; mt < 2; mt++)
                #pragma unroll
                for (int nt = 0; nt < 8; nt++)
                    mma_f16(acc[mt][nt], af[mt], bf[nt]);
        }
        __syncthreads();
    }

    // ---- fused epilogue: relu + per-row LN2/out-GEMM partials ----
    float part[4][8];
    #pragma unroll
    for (int pi = 0; pi < 4; pi++)
        #pragma unroll
        for (int j = 0; j < 8; j++) part[pi][j] = 0.f;

    #pragma unroll
    for (int nt = 0; nt < 8; nt++) {
        int col = n0 + wn * 64 + nt * 8 + tig * 2;
        float bl0 = __ldg(b1 + col);
        float bl1 = __ldg(b1 + col + 1);
        float w0[6], w1[6];
        #pragma unroll
        for (int c6 = 0; c6 < 6; c6++) {
            w0[c6] = __ldg(g_wp + c6 * CD_ + col);
            w1[c6] = __ldg(g_wp + c6 * CD_ + col + 1);
        }
        #pragma unroll
        for (int mt = 0; mt < 2; mt++) {
            #pragma unroll
            for (int pr = 0; pr < 2; pr++) {
                float v0 = fmaxf(acc[mt][nt][pr * 2 + 0] + bl0, 0.f);
                float v1 = fmaxf(acc[mt][nt][pr * 2 + 1] + bl1, 0.f);
                int pi = mt * 2 + pr;
                part[pi][6] += v0 + v1;
                part[pi][7] += v0 * v0 + v1 * v1;
                #pragma unroll
                for (int c6 = 0; c6 < 6; c6++)
                    part[pi][c6] += v0 * w0[c6] + v1 * w1[c6];
            }
        }
    }

    #pragma unroll
    for (int pi = 0; pi < 4; pi++)
        #pragma unroll
        for (int j = 0; j < 8; j++) {
            part[pi][j] += __shfl_xor_sync(0xffffffffu, part[pi][j], 1);
            part[pi][j] += __shfl_xor_sync(0xffffffffu, part[pi][j], 2);
        }

    if (tig == 0) {
        #pragma unroll
        for (int pi = 0; pi < 4; pi++) {
            int mt = pi >> 1, pr = pi & 1;
            int row = m0 + wm * 32 + mt * 16 + pr * 8 + gid;
            float* dst = g_acc + (size_t)row * 8;
            #pragma unroll
            for (int j = 0; j < 8; j++) atomicAdd(dst + j, part[pi][j]);
        }
    }
}

// ---------------- kernel 6: tiny finalize: LN2 stats + affine + biases -----
__global__ __launch_bounds__(256) void final2_kernel(const float* __restrict__ out_b,
                                                     float* __restrict__ out) {
    int i = blockIdx.x * blockDim.x + threadIdx.x;   // B*6
    if (i >= B_ * 6) return;
    int row = i / 6, c = i % 6;
    const float* a = g_acc + (size_t)row * 8;
    float p = a[c], s = a[6], q = a[7];
    float mu   = s * (1.0f / (float)CD_);
    float var  = q * (1.0f / (float)CD_) - mu * mu;
    float rstd = rsqrtf(var + EPS_);
    out[i] = rstd * p - rstd * mu * g_S[c] + g_T[c] + out_b[c] + g_bias[i];
}

// ---------------- launch ---------------------------------------------------
extern "C" void kernel_launch(void* const* d_in, const int* in_sizes, int n_in,
                              void* d_out, int out_size) {
    const float* encode     = (const float*)d_in[0];
    const float* credit_vec = (const float*)d_in[1];
    const float* meta_table = (const float*)d_in[2];
    const float* conv_w     = (const float*)d_in[3];
    const float* conv_b     = (const float*)d_in[4];
    const float* ln1_g      = (const float*)d_in[5];
    const float* ln1_b      = (const float*)d_in[6];
    const float* mlp1_w     = (const float*)d_in[7];
    const float* mlp1_b     = (const float*)d_in[8];
    const float* ln2_g      = (const float*)d_in[9];
    const float* ln2_b      = (const float*)d_in[10];
    const float* out_w      = (const float*)d_in[11];
    const float* out_b      = (const float*)d_in[12];
    const int*   meta_ids   = (const int*)d_in[13];
    const int*   cat_ids    = (const int*)d_in[14];
    const int*   cat_seg    = (const int*)d_in[15];
    float*       out        = (float*)d_out;

    const int smem_bytes = NSTG * STG_HLF * 2;   // 98304 B
    cudaFuncSetAttribute(gemm1_mma_kernel,
                         cudaFuncAttributeMaxDynamicSharedMemorySize, smem_bytes);

    zero_kernel<<<512, 256>>>();
    seg_kernel<<<NCAT_ / 8 / 256, 256>>>(meta_table, cat_ids, cat_seg);
    meta_kernel<<<B_ / 256, 256>>>(meta_table, credit_vec, conv_w, conv_b, meta_ids);
    ln1_kernel<<<B_, 128>>>(encode, ln1_g, ln1_b);
    w1pad_kernel<<<(CD_ * KP / 4 + 255) / 256, 256>>>(mlp1_w);
    prep_kernel<<<6, 256>>>(out_w, ln2_g, ln2_b);
    {
        dim3 grid(CD_ / 128, B_ / 128);
        gemm1_mma_kernel<<<grid, 256, smem_bytes>>>(mlp1_b);
    }
    final2_kernel<<<(B_ * 6 + 255) / 256, 256>>>(out_b, out);
}

// round 13
// speedup vs baseline: 7.4107x; 1.0386x over previous
#include <cuda_runtime.h>
#include <cuda_fp16.h>
#include <cstdint>

// ---------------- problem constants (pinned by the dataset) ----------------
#define B_    32768
#define H_    512
#define MD_   8
#define CD_   1024
#define KIN   532          // H + 20
#define KP    544          // KIN padded to 17 * 32
#define NCAT_ 262144
#define EPS_  1e-6f

// ---------------- scratch (static device allocations only) -----------------
__device__ __align__(128) float g_sums[B_ * MD_];
__device__ float g_counts[B_];
__device__ float g_meta[B_ * 20];
__device__ float g_bias[B_ * 6];
__device__ __align__(128) __half g_xn[(size_t)B_ * KP];   // LN1 out, fp16, k-permuted
__device__ __align__(128) __half g_w1p[CD_ * KP];         // mlp1_w fp16, k-permuted
__device__ __align__(128) float g_acc[(size_t)B_ * 8];    // per-row {p[6], sum, sumsq}
__device__ float g_wp[6 * CD_];                           // out_w * ln2_g
__device__ float g_S[6];                                  // row sums of g_wp
__device__ float g_T[6];                                  // out_w @ ln2_b

// k-permutation within each 16-half group: dest 4-half block r (g=r>>2,t=r&3)
// holds source halves {p, p+1, p+8, p+9} with p = 16g + 2t.

// ---------------- PTX helpers (baseline ISA only, no 'a' features) ---------
__device__ __forceinline__ uint32_t smem_u32(const void* p) {
    uint32_t a;
    asm("{ .reg .u64 t; cvta.to.shared.u64 t, %1; cvt.u32.u64 %0, t; }" : "=r"(a) : "l"(p));
    return a;
}
__device__ __forceinline__ void cp_async16(uint32_t saddr, const void* gaddr) {
    asm volatile("cp.async.cg.shared.global [%0], [%1], 16;" :: "r"(saddr), "l"(gaddr));
}
__device__ __forceinline__ void cp_commit() {
    asm volatile("cp.async.commit_group;");
}
template <int N>
__device__ __forceinline__ void cp_wait() {
    asm volatile("cp.async.wait_group %0;" :: "n"(N) : "memory");
}
__device__ __forceinline__ void mma_f16(float* c, const uint32_t* a, const uint32_t* b) {
    asm volatile(
        "mma.sync.aligned.m16n8k16.row.col.f32.f16.f16.f32 "
        "{%0,%1,%2,%3}, {%4,%5,%6,%7}, {%8,%9}, {%0,%1,%2,%3};"
        : "+f"(c[0]), "+f"(c[1]), "+f"(c[2]), "+f"(c[3])
        : "r"(a[0]), "r"(a[1]), "r"(a[2]), "r"(a[3]), "r"(b[0]), "r"(b[1]));
}
__device__ __forceinline__ uint32_t pack2h(float a, float b) {
    __half2 h = __floats2half2_rn(a, b);
    return *(uint32_t*)&h;
}

// ---------------- kernel A: fused prologue (zero | w1pad | prep) -----------
// independent preprocessing merged into one launch, split by blockIdx.x:
//   [0, ZBLK)              : zero g_sums/g_counts/g_acc (grid-stride)
//   [ZBLK, ZBLK+WBLK)      : w1 pad + fp16 + k-permute
//   [ZBLK+WBLK, +6)        : prep (W', S, T)
#define ZBLK 96
#define WBLK ((CD_ * KP / 4 + 255) / 256)    // 544
__global__ __launch_bounds__(256) void prologue_kernel(const float* __restrict__ w1,
                                                       const float* __restrict__ out_w,
                                                       const float* __restrict__ ln2g,
                                                       const float* __restrict__ ln2b) {
    int blk = blockIdx.x;
    int tid = threadIdx.x;
    if (blk < ZBLK) {
        int i = blk * 256 + tid;
        int stride = ZBLK * 256;
        for (int j = i; j < B_ * MD_; j += stride) g_sums[j] = 0.f;
        for (int j = i; j < B_; j += stride)       g_counts[j] = 0.f;
        for (int j = i; j < B_ * 8; j += stride)   g_acc[j] = 0.f;
    } else if (blk < ZBLK + WBLK) {
        int bi = (blk - ZBLK) * 256 + tid;        // dest 4-half block
        if (bi < CD_ * KP / 4) {
            int n = bi / (KP / 4);
            int r = bi % (KP / 4);
            int g = r >> 2, t = r & 3;
            int p = g * 16 + t * 2;
            const float* wrow = w1 + (size_t)n * KIN;
            float v0 = (p + 0 < KIN) ? wrow[p + 0] : 0.f;
            float v1 = (p + 1 < KIN) ? wrow[p + 1] : 0.f;
            float v2 = (p + 8 < KIN) ? wrow[p + 8] : 0.f;
            float v3 = (p + 9 < KIN) ? wrow[p + 9] : 0.f;
            uint2 u;
            u.x = pack2h(v0, v1);
            u.y = pack2h(v2, v3);
            ((uint2*)g_w1p)[bi] = u;
        }
    } else {
        int c = blk - ZBLK - WBLK;                // 0..5
        int lane = tid & 31, wid = tid >> 5;
        float s = 0.f, t = 0.f;
        for (int k = tid; k < CD_; k += 256) {
            float w  = out_w[c * CD_ + k];
            float wp = w * ln2g[k];
            g_wp[c * CD_ + k] = wp;
            s += wp;
            t += w * ln2b[k];
        }
        #pragma unroll
        for (int o = 16; o > 0; o >>= 1) {
            s += __shfl_down_sync(0xffffffffu, s, o);
            t += __shfl_down_sync(0xffffffffu, t, o);
        }
        __shared__ float rs[8], rt[8];
        if (lane == 0) { rs[wid] = s; rt[wid] = t; }
        __syncthreads();
        if (tid == 0) {
            float S = 0.f, T = 0.f;
            #pragma unroll
            for (int w = 0; w < 8; w++) { S += rs[w]; T += rt[w]; }
            g_S[c] = S; g_T[c] = T;
        }
    }
}

// ---------------- kernel 1: ragged segment sums (run-length compressed) ----
__global__ void seg_kernel(const float* __restrict__ table,
                           const int* __restrict__ cat_ids,
                           const int* __restrict__ cat_seg) {
    int t = blockIdx.x * blockDim.x + threadIdx.x;
    int base = t * 8;
    if (base >= NCAT_) return;

    float acc[8];
    int seg = cat_seg[base];
    {
        const float4* t4 = (const float4*)(table + (size_t)cat_ids[base] * MD_);
        float4 a = t4[0], b = t4[1];
        acc[0] = a.x; acc[1] = a.y; acc[2] = a.z; acc[3] = a.w;
        acc[4] = b.x; acc[5] = b.y; acc[6] = b.z; acc[7] = b.w;
    }
    float cnt = 1.f;

    #pragma unroll
    for (int j = 1; j < 8; j++) {
        int s2 = cat_seg[base + j];
        const float4* t4 = (const float4*)(table + (size_t)cat_ids[base + j] * MD_);
        float4 a = t4[0], b = t4[1];
        if (s2 != seg) {
            float* dst = g_sums + (size_t)seg * MD_;
            #pragma unroll
            for (int d = 0; d < 8; d++) atomicAdd(dst + d, acc[d]);
            atomicAdd(&g_counts[seg], cnt);
            seg = s2; cnt = 0.f;
            #pragma unroll
            for (int d = 0; d < 8; d++) acc[d] = 0.f;
        }
        acc[0] += a.x; acc[1] += a.y; acc[2] += a.z; acc[3] += a.w;
        acc[4] += b.x; acc[5] += b.y; acc[6] += b.z; acc[7] += b.w;
        cnt += 1.f;
    }
    float* dst = g_sums + (size_t)seg * MD_;
    #pragma unroll
    for (int d = 0; d < 8; d++) atomicAdd(dst + d, acc[d]);
    atomicAdd(&g_counts[seg], cnt);
}

// ---------------- kernel 2: meta conv/pool features + credit biases --------
__global__ void meta_kernel(const float* __restrict__ table,
                            const float* __restrict__ credit,
                            const float* __restrict__ conv_w,
                            const float* __restrict__ conv_b,
                            const int* __restrict__ meta_ids) {
    int b = blockIdx.x * blockDim.x + threadIdx.x;
    if (b >= B_) return;

    float mat[6][MD_];
    float cnt = fmaxf(g_counts[b], 1.0f);
    float inv = 1.0f / cnt;
    #pragma unroll
    for (int d = 0; d < MD_; d++) mat[0][d] = g_sums[(size_t)b * MD_ + d] * inv;
    #pragma unroll
    for (int j = 0; j < 5; j++) {
        int id = meta_ids[b * 5 + j];
        const float* row = table + (size_t)id * MD_;
        #pragma unroll
        for (int d = 0; d < MD_; d++) mat[j + 1][d] = row[d];
    }

    #pragma unroll
    for (int c = 0; c < 5; c++) {
        float conv[6];
        #pragma unroll
        for (int t = 0; t < 6; t++) {
            float s = conv_b[c];
            #pragma unroll
            for (int i = 0; i < 6; i++)
                #pragma unroll
                for (int k = 0; k < 3; k++)
                    s += conv_w[c * 18 + i * 3 + k] * mat[i][t + k];
            conv[t] = fmaxf(s, 0.f);
        }
        #pragma unroll
        for (int t = 0; t < 4; t++)
            g_meta[(size_t)b * 20 + c * 4 + t] =
                fmaxf(fmaxf(conv[t], conv[t + 1]), conv[t + 2]);
    }

    float cv[6], s = 0.f;
    #pragma unroll
    for (int c = 0; c < 6; c++) { cv[c] = credit[b * 6 + c]; s += cv[c]; }
    float invs = (s > 0.f) ? (1.0f / s) : 0.f;
    #pragma unroll
    for (int c = 0; c < 6; c++)
        g_bias[(size_t)b * 6 + c] = (s > 0.f) ? cv[c] * invs : (1.0f / 6.0f);
}

// ---------------- kernel 3: LN1 warp-per-row, no barriers ------------------
// 256 threads = 8 warps = 8 rows per block; butterfly shfl reduction,
// fp16 k-permute pack via shfl_xor(2) pair exchange.
__global__ __launch_bounds__(256) void ln1_kernel(const float* __restrict__ encode,
                                                  const float* __restrict__ g1,
                                                  const float* __restrict__ b1) {
    int lane = threadIdx.x & 31;
    int row = blockIdx.x * 8 + (threadIdx.x >> 5);

    const float4* erow = (const float4*)(encode + (size_t)row * H_);
    float4 xv[4];
    #pragma unroll
    for (int i = 0; i < 4; i++) xv[i] = erow[lane + 32 * i];
    float mv = (lane < 20) ? g_meta[(size_t)row * 20 + lane] : 0.f;

    float s = mv, sq = mv * mv;
    #pragma unroll
    for (int i = 0; i < 4; i++) {
        s  += xv[i].x + xv[i].y + xv[i].z + xv[i].w;
        sq += xv[i].x * xv[i].x + xv[i].y * xv[i].y
            + xv[i].z * xv[i].z + xv[i].w * xv[i].w;
    }
    #pragma unroll
    for (int o = 16; o > 0; o >>= 1) {
        s  += __shfl_xor_sync(0xffffffffu, s, o);
        sq += __shfl_xor_sync(0xffffffffu, sq, o);
    }
    float mean = s / (float)KIN;
    float var  = sq / (float)KIN - mean * mean;
    float rstd = rsqrtf(var + EPS_);

    uint2* xo = (uint2*)(g_xn + (size_t)row * KP);

    #pragma unroll
    for (int i = 0; i < 4; i++) {
        int j = lane + 32 * i;                 // src 4-half block
        float4 gg = ((const float4*)g1)[j];
        float4 bb = ((const float4*)b1)[j];
        float v0 = (xv[i].x - mean) * rstd * gg.x + bb.x;
        float v1 = (xv[i].y - mean) * rstd * gg.y + bb.y;
        float v2 = (xv[i].z - mean) * rstd * gg.z + bb.z;
        float v3 = (xv[i].w - mean) * rstd * gg.w + bb.w;
        uint32_t u0 = pack2h(v0, v1);
        uint32_t u1 = pack2h(v2, v3);
        uint32_t pu0 = __shfl_xor_sync(0xffffffffu, u0, 2);
        uint32_t pu1 = __shfl_xor_sync(0xffffffffu, u1, 2);
        int g = j >> 2, t = j & 3;
        uint2 u; int bi;
        if (t < 2) { u.x = u0;  u.y = pu0; bi = g * 4 + 2 * t; }
        else       { u.x = pu1; u.y = u1;  bi = g * 4 + 2 * t - 3; }
        xo[bi] = u;
    }

    // tail: dest blocks 128..135 cover src halves 512..543 (meta 20 + pad 12).
    // dest block 128+l needs src halves {512+si0..}, si = 16*(l>>2)+2*(l&3)+{0,1,8,9};
    // gather mv from owning lanes via shfl (all lanes participate).
    {
        int l7 = lane & 7;
        int sbase = 16 * (l7 >> 2) + 2 * (l7 & 3);
        int s0 = sbase, s1 = sbase + 1, s2 = sbase + 8, s3 = sbase + 9;
        float m0 = __shfl_sync(0xffffffffu, mv, s0 & 31);
        float m1 = __shfl_sync(0xffffffffu, mv, s1 & 31);
        float m2 = __shfl_sync(0xffffffffu, mv, s2 & 31);
        float m3 = __shfl_sync(0xffffffffu, mv, s3 & 31);
        if (lane < 8) {
            float t0 = (s0 < 20) ? (m0 - mean) * rstd * g1[H_ + s0] + b1[H_ + s0] : 0.f;
            float t1 = (s1 < 20) ? (m1 - mean) * rstd * g1[H_ + s1] + b1[H_ + s1] : 0.f;
            float t2 = (s2 < 20) ? (m2 - mean) * rstd * g1[H_ + s2] + b1[H_ + s2] : 0.f;
            float t3 = (s3 < 20) ? (m3 - mean) * rstd * g1[H_ + s3] + b1[H_ + s3] : 0.f;
            uint2 ut;
            ut.x = pack2h(t0, t1);
            ut.y = pack2h(t2, t3);
            xo[128 + lane] = ut;
        }
    }
}

// ---------------- kernel 5: fp16 mma.sync GEMM1 + fused LN2 partials -------
// CTA tile 128x128, BK=32 halves, 8 warps 4(m)x2(n), warp tile 32x64.
// 4-stage cp.async pipeline, 2 CTAs/SM for cross-CTA latency hiding.
#define BK      32
#define SROW    48                     // halves per smem row (96 B)
#define A_HALFS (128 * SROW)
#define STG_HLF (2 * A_HALFS)          // A + B per stage (24576 B)
#define NSTG    4
#define NCHUNK  17

extern __shared__ __align__(128) __half smem_h[];

__device__ __forceinline__ void load_chunk_h(uint32_t sbase, int st, int c,
                                             int m0, int n0, int tid) {
    uint32_t a_s = sbase + st * (STG_HLF * 2);
    uint32_t b_s = a_s + A_HALFS * 2;
    const __half* Ag = g_xn  + (size_t)m0 * KP + c * BK;
    const __half* Bg = g_w1p + (size_t)n0 * KP + c * BK;
    #pragma unroll
    for (int t = 0; t < 2; t++) {
        int u = tid + t * 256;
        int row = u >> 2, seg = u & 3;          // 16B (8-half) segments
        cp_async16(a_s + (row * SROW + seg * 8) * 2, Ag + (size_t)row * KP + seg * 8);
    }
    #pragma unroll
    for (int t = 0; t < 2; t++) {
        int u = tid + t * 256;
        int row = u >> 2, seg = u & 3;
        cp_async16(b_s + (row * SROW + seg * 8) * 2, Bg + (size_t)row * KP + seg * 8);
    }
    cp_commit();
}

__global__ __launch_bounds__(256, 2) void gemm1_mma_kernel(const float* __restrict__ b1) {
    const int tid  = threadIdx.x;
    const int warp = tid >> 5;
    const int lane = tid & 31;
    const int gid  = lane >> 2;          // 0..7
    const int tig  = lane & 3;           // 0..3
    const int wm   = warp >> 1;          // 0..3  (m)
    const int wn   = warp & 1;           // 0..1  (n)
    const int n0   = blockIdx.x * 128;
    const int m0   = blockIdx.y * 128;
    uint32_t sbase = smem_u32(smem_h);

    float acc[2][8][4];
    #pragma unroll
    for (int mt = 0; mt < 2; mt++)
        #pragma unroll
        for (int nt = 0; nt < 8; nt++)
            #pragma unroll
            for (int r = 0; r < 4; r++) acc[mt][nt][r] = 0.f;

    load_chunk_h(sbase, 0, 0, m0, n0, tid);
    load_chunk_h(sbase, 1, 1, m0, n0, tid);
    load_chunk_h(sbase, 2, 2, m0, n0, tid);

    for (int c = 0; c < NCHUNK; c++) {
        if (c + 3 < NCHUNK) {
            load_chunk_h(sbase, (c + 3) & (NSTG - 1), c + 3, m0, n0, tid);
            cp_wait<3>();
        } else if (c + 2 < NCHUNK) {
            cp_wait<2>();
        } else if (c + 1 < NCHUNK) {
            cp_wait<1>();
        } else {
            cp_wait<0>();
        }
        __syncthreads();

        const __half* As = smem_h + (c & (NSTG - 1)) * STG_HLF;
        const __half* Bs = As + A_HALFS;
        const __half* Arow0 = As + (wm * 32 + gid) * SROW + tig * 4;
        const __half* Brow0 = Bs + (wn * 64 + gid) * SROW + tig * 4;

        #pragma unroll
        for (int ks = 0; ks < 2; ks++) {
            const int k = ks * 16;
            uint32_t af[2][4], bf[8][2];
            #pragma unroll
            for (int mt = 0; mt < 2; mt++) {
                uint2 q0 = *(const uint2*)(Arow0 + mt * 16 * SROW + k);
                uint2 q1 = *(const uint2*)(Arow0 + (mt * 16 + 8) * SROW + k);
                af[mt][0] = q0.x; af[mt][1] = q1.x;
                af[mt][2] = q0.y; af[mt][3] = q1.y;
            }
            #pragma unroll
            for (int nt = 0; nt < 8; nt++) {
                uint2 qb = *(const uint2*)(Brow0 + nt * 8 * SROW + k);
                bf[nt][0] = qb.x; bf[nt][1] = qb.y;
            }
            #pragma unroll
            for (int mt = 0; mt < 2; mt++)
                #pragma unroll
                for (int nt = 0; nt < 8; nt++)
                    mma_f16(acc[mt][nt], af[mt], bf[nt]);
        }
        __syncthreads();
    }

    // ---- fused epilogue: relu + per-row LN2/out-GEMM partials ----
    float part[4][8];
    #pragma unroll
    for (int pi = 0; pi < 4; pi++)
        #pragma unroll
        for (int j = 0; j < 8; j++) part[pi][j] = 0.f;

    #pragma unroll
    for (int nt = 0; nt < 8; nt++) {
        int col = n0 + wn * 64 + nt * 8 + tig * 2;
        float bl0 = __ldg(b1 + col);
        float bl1 = __ldg(b1 + col + 1);
        float w0[6], w1[6];
        #pragma unroll
        for (int c6 = 0; c6 < 6; c6++) {
            w0[c6] = __ldg(g_wp + c6 * CD_ + col);
            w1[c6] = __ldg(g_wp + c6 * CD_ + col + 1);
        }
        #pragma unroll
        for (int mt = 0; mt < 2; mt++) {
            #pragma unroll
            for (int pr = 0; pr < 2; pr++) {
                float v0 = fmaxf(acc[mt][nt][pr * 2 + 0] + bl0, 0.f);
                float v1 = fmaxf(acc[mt][nt][pr * 2 + 1] + bl1, 0.f);
                int pi = mt * 2 + pr;
                part[pi][6] += v0 + v1;
                part[pi][7] += v0 * v0 + v1 * v1;
                #pragma unroll
                for (int c6 = 0; c6 < 6; c6++)
                    part[pi][c6] += v0 * w0[c6] + v1 * w1[c6];
            }
        }
    }

    #pragma unroll
    for (int pi = 0; pi < 4; pi++)
        #pragma unroll
        for (int j = 0; j < 8; j++) {
            part[pi][j] += __shfl_xor_sync(0xffffffffu, part[pi][j], 1);
            part[pi][j] += __shfl_xor_sync(0xffffffffu, part[pi][j], 2);
        }

    if (tig == 0) {
        #pragma unroll
        for (int pi = 0; pi < 4; pi++) {
            int mt = pi >> 1, pr = pi & 1;
            int row = m0 + wm * 32 + mt * 16 + pr * 8 + gid;
            float* dst = g_acc + (size_t)row * 8;
            #pragma unroll
            for (int j = 0; j < 8; j++) atomicAdd(dst + j, part[pi][j]);
        }
    }
}

// ---------------- kernel 6: tiny finalize: LN2 stats + affine + biases -----
__global__ __launch_bounds__(256) void final2_kernel(const float* __restrict__ out_b,
                                                     float* __restrict__ out) {
    int i = blockIdx.x * blockDim.x + threadIdx.x;   // B*6
    if (i >= B_ * 6) return;
    int row = i / 6, c = i % 6;
    const float* a = g_acc + (size_t)row * 8;
    float p = a[c], s = a[6], q = a[7];
    float mu   = s * (1.0f / (float)CD_);
    float var  = q * (1.0f / (float)CD_) - mu * mu;
    float rstd = rsqrtf(var + EPS_);
    out[i] = rstd * p - rstd * mu * g_S[c] + g_T[c] + out_b[c] + g_bias[i];
}

// ---------------- launch ---------------------------------------------------
extern "C" void kernel_launch(void* const* d_in, const int* in_sizes, int n_in,
                              void* d_out, int out_size) {
    const float* encode     = (const float*)d_in[0];
    const float* credit_vec = (const float*)d_in[1];
    const float* meta_table = (const float*)d_in[2];
    const float* conv_w     = (const float*)d_in[3];
    const float* conv_b     = (const float*)d_in[4];
    const float* ln1_g      = (const float*)d_in[5];
    const float* ln1_b      = (const float*)d_in[6];
    const float* mlp1_w     = (const float*)d_in[7];
    const float* mlp1_b     = (const float*)d_in[8];
    const float* ln2_g      = (const float*)d_in[9];
    const float* ln2_b      = (const float*)d_in[10];
    const float* out_w      = (const float*)d_in[11];
    const float* out_b      = (const float*)d_in[12];
    const int*   meta_ids   = (const int*)d_in[13];
    const int*   cat_ids    = (const int*)d_in[14];
    const int*   cat_seg    = (const int*)d_in[15];
    float*       out        = (float*)d_out;

    const int smem_bytes = NSTG * STG_HLF * 2;   // 98304 B
    cudaFuncSetAttribute(gemm1_mma_kernel,
                         cudaFuncAttributeMaxDynamicSharedMemorySize, smem_bytes);

    prologue_kernel<<<ZBLK + WBLK + 6, 256>>>(mlp1_w, out_w, ln2_g, ln2_b);
    seg_kernel<<<NCAT_ / 8 / 256, 256>>>(meta_table, cat_ids, cat_seg);
    meta_kernel<<<B_ / 256, 256>>>(meta_table, credit_vec, conv_w, conv_b, meta_ids);
    ln1_kernel<<<B_ / 8, 256>>>(encode, ln1_g, ln1_b);
    {
        dim3 grid(CD_ / 128, B_ / 128);
        gemm1_mma_kernel<<<grid, 256, smem_bytes>>>(mlp1_b);
    }
    final2_kernel<<<(B_ * 6 + 255) / 256, 256>>>(out_b, out);
}